// round 10
// baseline (speedup 1.0000x reference)
#include <cuda_runtime.h>

#define N_NODES 100000
#define N_EDGES 1000000
#define N_GRAPHS 512

#define TILE 128            // rows per block
#define P1   132            // transposed-tile pitch (floats), 16B-aligned

typedef unsigned long long u64;

// Scratch (device globals — no allocation allowed)
__device__ float g_h[N_NODES * 64];     // node features   (25.6 MB)
__device__ float g_agg[N_NODES * 64];   // gather target   (25.6 MB)
__device__ float g_e[N_EDGES * 64];     // edge embeddings, CSR-permuted (256 MB)
__device__ int   g_row[N_NODES + 1];    // CSR row offsets (by dst)
__device__ int   g_cur[N_NODES];        // fill cursors
__device__ int   g_src[N_EDGES];        // src node per CSR slot
__device__ int   g_pos[N_EDGES];        // edge id -> CSR slot

// ---------------- packed f32x2 helpers (sm_100+) ----------------
__device__ __forceinline__ u64 pk2(float x) {
    u64 r; asm("mov.b64 %0, {%1, %1};" : "=l"(r) : "f"(x)); return r;
}
__device__ __forceinline__ u64 pk(float x, float y) {
    u64 r; asm("mov.b64 %0, {%1, %2};" : "=l"(r) : "f"(x), "f"(y)); return r;
}
__device__ __forceinline__ float2 upk(u64 v) {
    float2 f; asm("mov.b64 {%0, %1}, %2;" : "=f"(f.x), "=f"(f.y) : "l"(v)); return f;
}
__device__ __forceinline__ u64 ffma2(u64 a, u64 b, u64 c) {
    u64 d; asm("fma.rn.f32x2 %0, %1, %2, %3;" : "=l"(d) : "l"(a), "l"(b), "l"(c)); return d;
}
__device__ __forceinline__ void red4(float* p, float x, float y, float z, float w) {
    asm volatile("red.global.add.v4.f32 [%0], {%1, %2, %3, %4};"
                 :: "l"(p), "f"(x), "f"(y), "f"(z), "f"(w) : "memory");
}

// ================= tile core =================
// Block: 256 threads, tile TILE(=128) rows x 64 cols.
// Thread (tr = tid>>3 in [0,32), tc = tid&7): rows tr*4..+4, cols tc*8..+8.
// acc[r*4+j]: row tr*4+r, col-pair (tc*8+2j, +1) as f32x2.
// Inputs transposed in smem sT[k][row], pitch P1; weights row-major sW[k][64].

__device__ __forceinline__ void fma16(u64* acc, float4 a, ulonglong2 wa, ulonglong2 wb) {
    u64 w[4] = { wa.x, wa.y, wb.x, wb.y };
    float ar[4] = { a.x, a.y, a.z, a.w };
    #pragma unroll
    for (int r = 0; r < 4; r++) {
        u64 av = pk2(ar[r]);
        #pragma unroll
        for (int j = 0; j < 4; j++) acc[r * 4 + j] = ffma2(av, w[j], acc[r * 4 + j]);
    }
}

// software-pipelined k-loop: loads for k+1/k+2 issue before FMAs of k/k+1
template<int K>
__device__ __forceinline__ void layer_run(const float* sT, const float* sW,
                                          u64* acc, int tr, int tc) {
    const float* aB = sT + tr * 4;
    const float* wB = sW + tc * 8;
    float4 a0 = *(const float4*)aB;
    ulonglong2 wa0 = *(const ulonglong2*)wB;
    ulonglong2 wb0 = *(const ulonglong2*)(wB + 4);
    #pragma unroll 1
    for (int k = 0; k < K; k += 2) {
        const float* aP1 = aB + (k + 1) * P1;
        const float* wP1 = wB + (k + 1) * 64;
        float4 a1 = *(const float4*)aP1;
        ulonglong2 wa1 = *(const ulonglong2*)wP1;
        ulonglong2 wb1 = *(const ulonglong2*)(wP1 + 4);
        fma16(acc, a0, wa0, wb0);
        int k2 = (k + 2 < K) ? k + 2 : k;
        const float* aP2 = aB + k2 * P1;
        const float* wP2 = wB + k2 * 64;
        a0 = *(const float4*)aP2;
        wa0 = *(const ulonglong2*)wP2;
        wb0 = *(const ulonglong2*)(wP2 + 4);
        fma16(acc, a1, wa1, wb1);
    }
}

__device__ __forceinline__ void init_bias16(u64* acc, const float* sB, int tc) {
    const u64* b = (const u64*)sB;
    u64 bv[4];
    #pragma unroll
    for (int j = 0; j < 4; j++) bv[j] = b[tc * 4 + j];
    #pragma unroll
    for (int r = 0; r < 4; r++)
        #pragma unroll
        for (int j = 0; j < 4; j++) acc[r * 4 + j] = bv[j];
}

__device__ __forceinline__ void relu16(u64* h) {
    #pragma unroll
    for (int i = 0; i < 16; i++) {
        float2 f = upk(h[i]);
        h[i] = pk(fmaxf(f.x, 0.f), fmaxf(f.y, 0.f));
    }
}

// store thread's 4x8 block transposed into sT[col][row]; column order swizzled
// by tc so the 8 tc-addresses are bank-disjoint (conflict-free STS.128)
__device__ __forceinline__ void store_T4(const u64* h, float* sT, int tr, int tc) {
    #pragma unroll
    for (int cc = 0; cc < 8; cc++) {
        int c = (cc + tc) & 7;
        int gc = tc * 8 + c, j = c >> 1;
        float v0, v1, v2, v3;
        if (c & 1) {
            v0 = upk(h[0*4+j]).y; v1 = upk(h[1*4+j]).y; v2 = upk(h[2*4+j]).y; v3 = upk(h[3*4+j]).y;
        } else {
            v0 = upk(h[0*4+j]).x; v1 = upk(h[1*4+j]).x; v2 = upk(h[2*4+j]).x; v3 = upk(h[3*4+j]).x;
        }
        *(float4*)(sT + gc * P1 + tr * 4) = make_float4(v0, v1, v2, v3);
    }
}

__device__ __forceinline__ void stage_copy(float* dst, const float* __restrict__ src, int n) {
    for (int i = threadIdx.x; i < n; i += 256) dst[i] = src[i];
}

// ---------------- CSR construction ----------------
__global__ void k_zero_row() {
    int i = blockIdx.x * 256 + threadIdx.x;
    if (i <= N_NODES) g_row[i] = 0;
}

__global__ void k_count(const int* __restrict__ ei) {
    int e = blockIdx.x * 256 + threadIdx.x;
    if (e < N_EDGES) atomicAdd(&g_row[ei[N_EDGES + e]], 1);
}

__global__ void __launch_bounds__(1024) k_scan() {
    __shared__ int warp_tot[32];
    __shared__ int carry_s, tot_s;
    int tid = threadIdx.x, lane = tid & 31, wid = tid >> 5;
    if (tid == 0) carry_s = 0;
    __syncthreads();
    for (int base = 0; base < N_NODES; base += 4096) {
        int idx = base + tid * 4;
        int v0 = (idx     < N_NODES) ? g_row[idx]     : 0;
        int v1 = (idx + 1 < N_NODES) ? g_row[idx + 1] : 0;
        int v2 = (idx + 2 < N_NODES) ? g_row[idx + 2] : 0;
        int v3 = (idx + 3 < N_NODES) ? g_row[idx + 3] : 0;
        int s0 = v0, s1 = s0 + v1, s2 = s1 + v2, s3 = s2 + v3;
        int tsum = s3;
        int incl = tsum;
        #pragma unroll
        for (int off = 1; off < 32; off <<= 1) {
            int t = __shfl_up_sync(0xffffffff, incl, off);
            if (lane >= off) incl += t;
        }
        if (lane == 31) warp_tot[wid] = incl;
        __syncthreads();
        if (wid == 0) {
            int w = warp_tot[lane];
            int wi = w;
            #pragma unroll
            for (int off = 1; off < 32; off <<= 1) {
                int t = __shfl_up_sync(0xffffffff, wi, off);
                if (lane >= off) wi += t;
            }
            warp_tot[lane] = wi - w;
            if (lane == 31) tot_s = wi;
        }
        __syncthreads();
        int eb = carry_s + warp_tot[wid] + (incl - tsum);
        if (idx     < N_NODES) { g_row[idx]     = eb;      g_cur[idx]     = eb; }
        if (idx + 1 < N_NODES) { g_row[idx + 1] = eb + s0; g_cur[idx + 1] = eb + s0; }
        if (idx + 2 < N_NODES) { g_row[idx + 2] = eb + s1; g_cur[idx + 2] = eb + s1; }
        if (idx + 3 < N_NODES) { g_row[idx + 3] = eb + s2; g_cur[idx + 3] = eb + s2; }
        __syncthreads();
        if (tid == 0) carry_s += tot_s;
        __syncthreads();
    }
    if (tid == 0) g_row[N_NODES] = N_EDGES;
}

__global__ void k_fill(const int* __restrict__ ei) {
    int e = blockIdx.x * 256 + threadIdx.x;
    if (e >= N_EDGES) return;
    int src = ei[e];
    int dst = ei[N_EDGES + e];
    int p = atomicAdd(&g_cur[dst], 1);
    g_src[p] = src;
    g_pos[e] = p;
}

// ---------------- MLP kernels ----------------
// smem: [sT 64*P1 | sW0 KIN*64 | sW1 64*64 | b0 64 | b1 64]

__global__ void __launch_bounds__(256, 3)
k_node_init(const float* __restrict__ x,
            const float* __restrict__ w0, const float* __restrict__ b0,
            const float* __restrict__ w1, const float* __restrict__ b1) {
    extern __shared__ float smem[];
    float* sT  = smem;
    float* sW0 = sT + 64 * P1;
    float* sW1 = sW0 + 32 * 64;
    float* sB0 = sW1 + 64 * 64;
    float* sB1 = sB0 + 64;
    stage_copy(sW0, w0, 32 * 64); stage_copy(sW1, w1, 64 * 64);
    stage_copy(sB0, b0, 64);      stage_copy(sB1, b1, 64);
    int tid = threadIdx.x, tc = tid & 7, tr = tid >> 3;
    long long base = (long long)blockIdx.x * TILE;
    for (int i = tid; i < TILE * 8; i += 256) {
        int row = i >> 3, k4 = i & 7;
        long long gr = base + row; if (gr >= N_NODES) gr = N_NODES - 1;
        float4 v = ((const float4*)(x + gr * 32))[k4];
        int k = k4 * 4;
        sT[(k + 0) * P1 + row] = v.x;
        sT[(k + 1) * P1 + row] = v.y;
        sT[(k + 2) * P1 + row] = v.z;
        sT[(k + 3) * P1 + row] = v.w;
    }
    __syncthreads();
    u64 h[16];
    init_bias16(h, sB0, tc);
    layer_run<32>(sT, sW0, h, tr, tc);
    relu16(h);
    __syncthreads();
    store_T4(h, sT, tr, tc);
    __syncthreads();
    u64 acc[16];
    init_bias16(acc, sB1, tc);
    layer_run<64>(sT, sW1, acc, tr, tc);
    #pragma unroll
    for (int r = 0; r < 4; r++) {
        long long row = base + tr * 4 + r;
        if (row < N_NODES) {
            float2 a = upk(acc[r*4]), b = upk(acc[r*4+1]), c = upk(acc[r*4+2]), d = upk(acc[r*4+3]);
            float4* o = (float4*)(g_h + row * 64 + tc * 8);
            o[0] = make_float4(a.x, a.y, b.x, b.y);
            o[1] = make_float4(c.x, c.y, d.x, d.y);
        }
    }
}

__global__ void __launch_bounds__(256, 3)
k_edge_init(const float* __restrict__ ea,
            const float* __restrict__ w0, const float* __restrict__ b0,
            const float* __restrict__ w1, const float* __restrict__ b1) {
    extern __shared__ float smem[];
    float* sT  = smem;
    float* sW0 = sT + 64 * P1;
    float* sW1 = sW0 + 16 * 64;
    float* sB0 = sW1 + 64 * 64;
    float* sB1 = sB0 + 64;
    stage_copy(sW0, w0, 16 * 64); stage_copy(sW1, w1, 64 * 64);
    stage_copy(sB0, b0, 64);      stage_copy(sB1, b1, 64);
    int tid = threadIdx.x, tc = tid & 7, tr = tid >> 3;
    long long base = (long long)blockIdx.x * TILE;
    for (int i = tid; i < TILE * 4; i += 256) {
        int row = i >> 2, k4 = i & 3;
        long long gr = base + row; if (gr >= N_EDGES) gr = N_EDGES - 1;
        float4 v = ((const float4*)(ea + gr * 16))[k4];
        int k = k4 * 4;
        sT[(k + 0) * P1 + row] = v.x;
        sT[(k + 1) * P1 + row] = v.y;
        sT[(k + 2) * P1 + row] = v.z;
        sT[(k + 3) * P1 + row] = v.w;
    }
    __syncthreads();
    u64 h[16];
    init_bias16(h, sB0, tc);
    layer_run<16>(sT, sW0, h, tr, tc);
    relu16(h);
    __syncthreads();
    store_T4(h, sT, tr, tc);
    __syncthreads();
    u64 acc[16];
    init_bias16(acc, sB1, tc);
    layer_run<64>(sT, sW1, acc, tr, tc);
    #pragma unroll
    for (int r = 0; r < 4; r++) {
        long long row = base + tr * 4 + r;
        if (row < N_EDGES) {
            int p = __ldg(&g_pos[row]);
            float2 a = upk(acc[r*4]), b = upk(acc[r*4+1]), c = upk(acc[r*4+2]), d = upk(acc[r*4+3]);
            float4* o = (float4*)(g_e + (size_t)p * 64 + tc * 8);
            __stcs(&o[0], make_float4(a.x, a.y, b.x, b.y));
            __stcs(&o[1], make_float4(c.x, c.y, d.x, d.y));
        }
    }
}

// conv staging: t = agg + 1.1*h, transposed
__device__ __forceinline__ void stage_conv(float* sT, long long base, long long limit) {
    for (int i = threadIdx.x; i < TILE * 16; i += 256) {
        int row = i >> 4, k4 = i & 15;
        long long gr = base + row; if (gr >= limit) gr = limit - 1;
        float4 a = ((const float4*)(g_agg + gr * 64))[k4];
        float4 h = ((const float4*)(g_h   + gr * 64))[k4];
        int k = k4 * 4;
        sT[(k + 0) * P1 + row] = fmaf(1.1f, h.x, a.x);
        sT[(k + 1) * P1 + row] = fmaf(1.1f, h.y, a.y);
        sT[(k + 2) * P1 + row] = fmaf(1.1f, h.z, a.z);
        sT[(k + 3) * P1 + row] = fmaf(1.1f, h.w, a.w);
    }
}

__global__ void __launch_bounds__(256, 3)
k_node_update(const float* __restrict__ w0, const float* __restrict__ b0,
              const float* __restrict__ w1, const float* __restrict__ b1) {
    extern __shared__ float smem[];
    float* sT  = smem;
    float* sW0 = sT + 64 * P1;
    float* sW1 = sW0 + 64 * 64;
    float* sB0 = sW1 + 64 * 64;
    float* sB1 = sB0 + 64;
    stage_copy(sW0, w0, 64 * 64); stage_copy(sW1, w1, 64 * 64);
    stage_copy(sB0, b0, 64);      stage_copy(sB1, b1, 64);
    int tid = threadIdx.x, tc = tid & 7, tr = tid >> 3;
    long long base = (long long)blockIdx.x * TILE;
    stage_conv(sT, base, N_NODES);
    __syncthreads();
    u64 h[16];
    init_bias16(h, sB0, tc);
    layer_run<64>(sT, sW0, h, tr, tc);
    relu16(h);
    __syncthreads();
    store_T4(h, sT, tr, tc);
    __syncthreads();
    u64 acc[16];
    init_bias16(acc, sB1, tc);
    layer_run<64>(sT, sW1, acc, tr, tc);
    #pragma unroll
    for (int r = 0; r < 4; r++) {
        long long row = base + tr * 4 + r;
        if (row < N_NODES) {
            float4* o = (float4*)(g_h + row * 64 + tc * 8);
            float4 h0 = o[0], h1 = o[1];
            float2 a = upk(acc[r*4]), b = upk(acc[r*4+1]), c = upk(acc[r*4+2]), d = upk(acc[r*4+3]);
            o[0] = make_float4(fmaxf(h0.x + a.x, 0.f), fmaxf(h0.y + a.y, 0.f),
                               fmaxf(h0.z + b.x, 0.f), fmaxf(h0.w + b.y, 0.f));
            o[1] = make_float4(fmaxf(h1.x + c.x, 0.f), fmaxf(h1.y + c.y, 0.f),
                               fmaxf(h1.z + d.x, 0.f), fmaxf(h1.w + d.y, 0.f));
        }
    }
}

__global__ void __launch_bounds__(256, 3)
k_node_final(const int* __restrict__ batch,
             const float* __restrict__ w0, const float* __restrict__ b0,
             const float* __restrict__ w1, const float* __restrict__ b1,
             float* __restrict__ out) {
    extern __shared__ float smem[];
    float* sT  = smem;
    float* sW0 = sT + 64 * P1;
    float* sW1 = sW0 + 64 * 64;
    float* sB0 = sW1 + 64 * 64;
    float* sB1 = sB0 + 64;
    stage_copy(sW0, w0, 64 * 64); stage_copy(sW1, w1, 64 * 64);
    stage_copy(sB0, b0, 64);      stage_copy(sB1, b1, 64);
    int tid = threadIdx.x, tc = tid & 7, tr = tid >> 3;
    long long base = (long long)blockIdx.x * TILE;
    stage_conv(sT, base, N_NODES);
    __syncthreads();
    u64 h[16];
    init_bias16(h, sB0, tc);
    layer_run<64>(sT, sW0, h, tr, tc);
    relu16(h);
    __syncthreads();
    store_T4(h, sT, tr, tc);
    __syncthreads();
    u64 acc[16];
    init_bias16(acc, sB1, tc);
    layer_run<64>(sT, sW1, acc, tr, tc);
    #pragma unroll
    for (int r = 0; r < 4; r++) {
        long long row = base + tr * 4 + r;
        if (row < N_NODES) {
            int bg = __ldg(&batch[row]);
            float* p = out + (size_t)bg * 64 + tc * 8;
            float2 a = upk(acc[r*4]), b = upk(acc[r*4+1]), c = upk(acc[r*4+2]), d = upk(acc[r*4+3]);
            red4(p,     a.x, a.y, b.x, b.y);
            red4(p + 4, c.x, c.y, d.x, d.y);
        }
    }
}

__global__ void k_zero_out(float4* out) {
    int i = blockIdx.x * 256 + threadIdx.x;
    out[i] = make_float4(0.f, 0.f, 0.f, 0.f);
}

// Gather (atomic-free, sequential e): 16 lanes per node.
__global__ void __launch_bounds__(256)
k_gather() {
    int gid = blockIdx.x * 256 + threadIdx.x;
    int n = gid >> 4, lane = gid & 15;
    if (n >= N_NODES) return;
    int beg = g_row[n], end = g_row[n + 1];
    float4 acc = make_float4(0.f, 0.f, 0.f, 0.f);
    for (int s = beg; s < end; s++) {
        int src = __ldg(&g_src[s]);
        float4 ev = __ldcs((const float4*)g_e + (size_t)s * 16 + lane);
        float4 hv = __ldg((const float4*)g_h + (size_t)src * 16 + lane);
        acc.x += fmaxf(hv.x + ev.x, 0.f);
        acc.y += fmaxf(hv.y + ev.y, 0.f);
        acc.z += fmaxf(hv.z + ev.z, 0.f);
        acc.w += fmaxf(hv.w + ev.w, 0.f);
    }
    ((float4*)g_agg)[(size_t)n * 16 + lane] = acc;
}

extern "C" void kernel_launch(void* const* d_in, const int* in_sizes, int n_in,
                              void* d_out, int out_size) {
    const float* x   = (const float*)d_in[0];
    const int*   ei  = (const int*)d_in[1];
    const float* ea  = (const float*)d_in[2];
    const int*   bat = (const int*)d_in[3];
    const float* wn0 = (const float*)d_in[4],  *bn0 = (const float*)d_in[5];
    const float* wn1 = (const float*)d_in[6],  *bn1 = (const float*)d_in[7];
    const float* we0 = (const float*)d_in[8],  *be0 = (const float*)d_in[9];
    const float* we1 = (const float*)d_in[10], *be1 = (const float*)d_in[11];
    const float* cw0 = (const float*)d_in[12], *cb0 = (const float*)d_in[13];
    const float* cw1 = (const float*)d_in[14], *cb1 = (const float*)d_in[15];
    const float* lw0 = (const float*)d_in[16], *lb0 = (const float*)d_in[17];
    const float* lw1 = (const float*)d_in[18], *lb1 = (const float*)d_in[19];
    float* out = (float*)d_out;

    const int SM_NODE = (64 * P1 + 32 * 64 + 64 * 64 + 128) * 4;
    const int SM_EDGE = (64 * P1 + 16 * 64 + 64 * 64 + 128) * 4;
    const int SM_CONV = (64 * P1 + 64 * 64 + 64 * 64 + 128) * 4;
    cudaFuncSetAttribute(k_node_init,   cudaFuncAttributeMaxDynamicSharedMemorySize, SM_NODE);
    cudaFuncSetAttribute(k_edge_init,   cudaFuncAttributeMaxDynamicSharedMemorySize, SM_EDGE);
    cudaFuncSetAttribute(k_node_update, cudaFuncAttributeMaxDynamicSharedMemorySize, SM_CONV);
    cudaFuncSetAttribute(k_node_final,  cudaFuncAttributeMaxDynamicSharedMemorySize, SM_CONV);

    const int E256       = (N_EDGES + 255) / 256;
    const int NODE_TILES = (N_NODES + TILE - 1) / TILE;   // 782
    const int EDGE_TILES = (N_EDGES + TILE - 1) / TILE;   // 7813
    const int GATH_BLOCKS = (N_NODES * 16 + 255) / 256;

    // launch index 3 = k_node_init (the slot ncu captures)
    k_zero_row<<<(N_NODES + 1 + 255) / 256, 256>>>();                       // 0
    k_count<<<E256, 256>>>(ei);                                              // 1
    k_scan<<<1, 1024>>>();                                                   // 2
    k_node_init<<<NODE_TILES, 256, SM_NODE>>>(x, wn0, bn0, wn1, bn1);        // 3 <- profiled
    k_fill<<<E256, 256>>>(ei);                                               // 4
    k_edge_init<<<EDGE_TILES, 256, SM_EDGE>>>(ea, we0, be0, we1, be1);       // 5
    k_zero_out<<<(N_GRAPHS * 64 / 4) / 256, 256>>>((float4*)out);            // 6

    for (int l = 0; l < 3; l++) {
        k_gather<<<GATH_BLOCKS, 256>>>();
        k_node_update<<<NODE_TILES, 256, SM_CONV>>>(cw0 + l * 64 * 64, cb0 + l * 64,
                                                    cw1 + l * 64 * 64, cb1 + l * 64);
    }
    k_gather<<<GATH_BLOCKS, 256>>>();
    k_node_final<<<NODE_TILES, 256, SM_CONV>>>(bat, lw0, lb0, lw1, lb1, out);
}

// round 11
// speedup vs baseline: 1.1866x; 1.1866x over previous
#include <cuda_runtime.h>

#define N_NODES 100000
#define N_EDGES 1000000
#define N_GRAPHS 512

#define TILE 256            // rows per block
#define P1   260            // transposed-tile pitch (floats)

typedef unsigned long long u64;

// Scratch (device globals — no allocation allowed)
__device__ float g_h[N_NODES * 64];     // node features   (25.6 MB)
__device__ float g_agg[N_NODES * 64];   // gather target   (25.6 MB)
__device__ float g_e[N_EDGES * 64];     // edge embeddings, CSR-permuted (256 MB)
__device__ int   g_row[N_NODES + 1];    // CSR row offsets (by dst)
__device__ int   g_cur[N_NODES];        // fill cursors
__device__ int   g_src[N_EDGES];        // src node per CSR slot
__device__ int   g_pos[N_EDGES];        // edge id -> CSR slot

// ---------------- packed f32x2 helpers (sm_100+) ----------------
__device__ __forceinline__ u64 pk2(float x) {
    u64 r; asm("mov.b64 %0, {%1, %1};" : "=l"(r) : "f"(x)); return r;
}
__device__ __forceinline__ u64 pk(float x, float y) {
    u64 r; asm("mov.b64 %0, {%1, %2};" : "=l"(r) : "f"(x), "f"(y)); return r;
}
__device__ __forceinline__ float2 upk(u64 v) {
    float2 f; asm("mov.b64 {%0, %1}, %2;" : "=f"(f.x), "=f"(f.y) : "l"(v)); return f;
}
__device__ __forceinline__ u64 ffma2(u64 a, u64 b, u64 c) {
    u64 d; asm("fma.rn.f32x2 %0, %1, %2, %3;" : "=l"(d) : "l"(a), "l"(b), "l"(c)); return d;
}
__device__ __forceinline__ void red4(float* p, float x, float y, float z, float w) {
    asm volatile("red.global.add.v4.f32 [%0], {%1, %2, %3, %4};"
                 :: "l"(p), "f"(x), "f"(y), "f"(z), "f"(w) : "memory");
}

// ================= tile core =================
// Block: 256 threads = 8 warps, tile 256 rows x 64 cols.
// Warp wid owns col-block [wid*8, wid*8+8): W loads are warp-BROADCAST (1 wf).
// Lane owns rows {lane*4..+4} and {128+lane*4..+4}: A loads lane-consecutive
// (conflict-free). acc[r*4+j]: r<4 group0 rows, r>=4 group1; j = col-pair.

template<int K>
__device__ __forceinline__ void layer_warp(const float* sT, const float* sW,
                                           u64* acc, int lane, int wid) {
    const float* aB = sT + lane * 4;
    const float* wB = sW + wid * 8;
    #pragma unroll 2
    for (int k = 0; k < K; k++) {
        float4 a0 = *(const float4*)(aB + k * P1);
        float4 a1 = *(const float4*)(aB + k * P1 + 128);
        const ulonglong2* wP = (const ulonglong2*)(wB + k * 64);
        ulonglong2 wA = wP[0], wBv = wP[1];
        u64 w[4] = { wA.x, wA.y, wBv.x, wBv.y };
        float ar[8] = { a0.x, a0.y, a0.z, a0.w, a1.x, a1.y, a1.z, a1.w };
        #pragma unroll
        for (int r = 0; r < 8; r++) {
            u64 av = pk2(ar[r]);
            #pragma unroll
            for (int j = 0; j < 4; j++) acc[r * 4 + j] = ffma2(av, w[j], acc[r * 4 + j]);
        }
    }
}

__device__ __forceinline__ void init_bias(u64* acc, const float* sB, int wid) {
    const u64* b = (const u64*)sB;
    u64 bv[4];
    #pragma unroll
    for (int j = 0; j < 4; j++) bv[j] = b[wid * 4 + j];   // broadcast
    #pragma unroll
    for (int r = 0; r < 8; r++)
        #pragma unroll
        for (int j = 0; j < 4; j++) acc[r * 4 + j] = bv[j];
}

__device__ __forceinline__ void relu32(u64* h) {
    #pragma unroll
    for (int i = 0; i < 32; i++) {
        float2 f = upk(h[i]);
        h[i] = pk(fmaxf(f.x, 0.f), fmaxf(f.y, 0.f));
    }
}

// transpose-store thread's 8 rows x 8 cols into sT[col][row]; all lanes write
// the same column -> lane-consecutive STS.128, conflict-free
__device__ __forceinline__ void store_T(const u64* h, float* sT, int lane, int wid) {
    #pragma unroll
    for (int c = 0; c < 8; c++) {
        int gc = wid * 8 + c, j = c >> 1;
        float g0[4], g1[4];
        if (c & 1) {
            #pragma unroll
            for (int r = 0; r < 4; r++) { g0[r] = upk(h[r*4+j]).y; g1[r] = upk(h[(r+4)*4+j]).y; }
        } else {
            #pragma unroll
            for (int r = 0; r < 4; r++) { g0[r] = upk(h[r*4+j]).x; g1[r] = upk(h[(r+4)*4+j]).x; }
        }
        *(float4*)(sT + gc * P1 + lane * 4)       = make_float4(g0[0], g0[1], g0[2], g0[3]);
        *(float4*)(sT + gc * P1 + 128 + lane * 4) = make_float4(g1[0], g1[1], g1[2], g1[3]);
    }
}

__device__ __forceinline__ void stage_copy(float* dst, const float* __restrict__ src, int n) {
    for (int i = threadIdx.x; i < n; i += 256) dst[i] = src[i];
}

// row index of acc group r (0..7) for this lane
__device__ __forceinline__ int row_of(int lane, int r) {
    return (r < 4) ? lane * 4 + r : 128 + lane * 4 + (r - 4);
}

// ---------------- CSR construction ----------------
__global__ void k_zero_row() {
    int i = blockIdx.x * 256 + threadIdx.x;
    if (i <= N_NODES) g_row[i] = 0;
}

__global__ void k_count(const int* __restrict__ ei) {
    int e = blockIdx.x * 256 + threadIdx.x;
    if (e < N_EDGES) atomicAdd(&g_row[ei[N_EDGES + e]], 1);
}

__global__ void __launch_bounds__(1024) k_scan() {
    __shared__ int warp_tot[32];
    __shared__ int carry_s, tot_s;
    int tid = threadIdx.x, lane = tid & 31, wid = tid >> 5;
    if (tid == 0) carry_s = 0;
    __syncthreads();
    for (int base = 0; base < N_NODES; base += 4096) {
        int idx = base + tid * 4;
        int v0 = (idx     < N_NODES) ? g_row[idx]     : 0;
        int v1 = (idx + 1 < N_NODES) ? g_row[idx + 1] : 0;
        int v2 = (idx + 2 < N_NODES) ? g_row[idx + 2] : 0;
        int v3 = (idx + 3 < N_NODES) ? g_row[idx + 3] : 0;
        int s0 = v0, s1 = s0 + v1, s2 = s1 + v2, s3 = s2 + v3;
        int tsum = s3;
        int incl = tsum;
        #pragma unroll
        for (int off = 1; off < 32; off <<= 1) {
            int t = __shfl_up_sync(0xffffffff, incl, off);
            if (lane >= off) incl += t;
        }
        if (lane == 31) warp_tot[wid] = incl;
        __syncthreads();
        if (wid == 0) {
            int w = warp_tot[lane];
            int wi = w;
            #pragma unroll
            for (int off = 1; off < 32; off <<= 1) {
                int t = __shfl_up_sync(0xffffffff, wi, off);
                if (lane >= off) wi += t;
            }
            warp_tot[lane] = wi - w;
            if (lane == 31) tot_s = wi;
        }
        __syncthreads();
        int eb = carry_s + warp_tot[wid] + (incl - tsum);
        if (idx     < N_NODES) { g_row[idx]     = eb;      g_cur[idx]     = eb; }
        if (idx + 1 < N_NODES) { g_row[idx + 1] = eb + s0; g_cur[idx + 1] = eb + s0; }
        if (idx + 2 < N_NODES) { g_row[idx + 2] = eb + s1; g_cur[idx + 2] = eb + s1; }
        if (idx + 3 < N_NODES) { g_row[idx + 3] = eb + s2; g_cur[idx + 3] = eb + s2; }
        __syncthreads();
        if (tid == 0) carry_s += tot_s;
        __syncthreads();
    }
    if (tid == 0) g_row[N_NODES] = N_EDGES;
}

__global__ void k_fill(const int* __restrict__ ei) {
    int e = blockIdx.x * 256 + threadIdx.x;
    if (e >= N_EDGES) return;
    int src = ei[e];
    int dst = ei[N_EDGES + e];
    int p = atomicAdd(&g_cur[dst], 1);
    g_src[p] = src;
    g_pos[e] = p;
}

// ---------------- MLP kernels ----------------
// smem: [sT 64*P1 | sW0 KIN*64 | sW1 64*64 | b0 64 | b1 64]

__global__ void __launch_bounds__(256, 2)
k_node_init(const float* __restrict__ x,
            const float* __restrict__ w0, const float* __restrict__ b0,
            const float* __restrict__ w1, const float* __restrict__ b1) {
    extern __shared__ float smem[];
    float* sT  = smem;
    float* sW0 = sT + 64 * P1;
    float* sW1 = sW0 + 32 * 64;
    float* sB0 = sW1 + 64 * 64;
    float* sB1 = sB0 + 64;
    stage_copy(sW0, w0, 32 * 64); stage_copy(sW1, w1, 64 * 64);
    stage_copy(sB0, b0, 64);      stage_copy(sB1, b1, 64);
    int tid = threadIdx.x, lane = tid & 31, wid = tid >> 5;
    long long base = (long long)blockIdx.x * TILE;
    for (int i = tid; i < TILE * 8; i += 256) {
        int row = i >> 3, k4 = i & 7;
        long long gr = base + row; if (gr >= N_NODES) gr = N_NODES - 1;
        float4 v = ((const float4*)(x + gr * 32))[k4];
        int k = k4 * 4;
        sT[(k + 0) * P1 + row] = v.x;
        sT[(k + 1) * P1 + row] = v.y;
        sT[(k + 2) * P1 + row] = v.z;
        sT[(k + 3) * P1 + row] = v.w;
    }
    __syncthreads();
    u64 h[32];
    init_bias(h, sB0, wid);
    layer_warp<32>(sT, sW0, h, lane, wid);
    relu32(h);
    __syncthreads();
    store_T(h, sT, lane, wid);
    __syncthreads();
    u64 acc[32];
    init_bias(acc, sB1, wid);
    layer_warp<64>(sT, sW1, acc, lane, wid);
    #pragma unroll
    for (int r = 0; r < 8; r++) {
        long long row = base + row_of(lane, r);
        if (row < N_NODES) {
            float2 a = upk(acc[r*4]), b = upk(acc[r*4+1]), c = upk(acc[r*4+2]), d = upk(acc[r*4+3]);
            float4* o = (float4*)(g_h + row * 64 + wid * 8);
            o[0] = make_float4(a.x, a.y, b.x, b.y);
            o[1] = make_float4(c.x, c.y, d.x, d.y);
        }
    }
}

__global__ void __launch_bounds__(256, 2)
k_edge_init(const float* __restrict__ ea,
            const float* __restrict__ w0, const float* __restrict__ b0,
            const float* __restrict__ w1, const float* __restrict__ b1) {
    extern __shared__ float smem[];
    float* sT  = smem;
    float* sW0 = sT + 64 * P1;
    float* sW1 = sW0 + 16 * 64;
    float* sB0 = sW1 + 64 * 64;
    float* sB1 = sB0 + 64;
    stage_copy(sW0, w0, 16 * 64); stage_copy(sW1, w1, 64 * 64);
    stage_copy(sB0, b0, 64);      stage_copy(sB1, b1, 64);
    int tid = threadIdx.x, lane = tid & 31, wid = tid >> 5;
    long long base = (long long)blockIdx.x * TILE;
    for (int i = tid; i < TILE * 4; i += 256) {
        int row = i >> 2, k4 = i & 3;
        long long gr = base + row; if (gr >= N_EDGES) gr = N_EDGES - 1;
        float4 v = ((const float4*)(ea + gr * 16))[k4];
        int k = k4 * 4;
        sT[(k + 0) * P1 + row] = v.x;
        sT[(k + 1) * P1 + row] = v.y;
        sT[(k + 2) * P1 + row] = v.z;
        sT[(k + 3) * P1 + row] = v.w;
    }
    __syncthreads();
    u64 h[32];
    init_bias(h, sB0, wid);
    layer_warp<16>(sT, sW0, h, lane, wid);
    relu32(h);
    __syncthreads();
    store_T(h, sT, lane, wid);
    __syncthreads();
    u64 acc[32];
    init_bias(acc, sB1, wid);
    layer_warp<64>(sT, sW1, acc, lane, wid);
    #pragma unroll
    for (int r = 0; r < 8; r++) {
        long long row = base + row_of(lane, r);
        if (row < N_EDGES) {
            int p = __ldg(&g_pos[row]);
            float2 a = upk(acc[r*4]), b = upk(acc[r*4+1]), c = upk(acc[r*4+2]), d = upk(acc[r*4+3]);
            float4* o = (float4*)(g_e + (size_t)p * 64 + wid * 8);
            __stcs(&o[0], make_float4(a.x, a.y, b.x, b.y));
            __stcs(&o[1], make_float4(c.x, c.y, d.x, d.y));
        }
    }
}

// conv staging: t = agg + 1.1*h, transposed
__device__ __forceinline__ void stage_conv(float* sT, long long base, long long limit) {
    for (int i = threadIdx.x; i < TILE * 16; i += 256) {
        int row = i >> 4, k4 = i & 15;
        long long gr = base + row; if (gr >= limit) gr = limit - 1;
        float4 a = ((const float4*)(g_agg + gr * 64))[k4];
        float4 h = ((const float4*)(g_h   + gr * 64))[k4];
        int k = k4 * 4;
        sT[(k + 0) * P1 + row] = fmaf(1.1f, h.x, a.x);
        sT[(k + 1) * P1 + row] = fmaf(1.1f, h.y, a.y);
        sT[(k + 2) * P1 + row] = fmaf(1.1f, h.z, a.z);
        sT[(k + 3) * P1 + row] = fmaf(1.1f, h.w, a.w);
    }
}

__global__ void __launch_bounds__(256, 2)
k_node_update(const float* __restrict__ w0, const float* __restrict__ b0,
              const float* __restrict__ w1, const float* __restrict__ b1) {
    extern __shared__ float smem[];
    float* sT  = smem;
    float* sW0 = sT + 64 * P1;
    float* sW1 = sW0 + 64 * 64;
    float* sB0 = sW1 + 64 * 64;
    float* sB1 = sB0 + 64;
    stage_copy(sW0, w0, 64 * 64); stage_copy(sW1, w1, 64 * 64);
    stage_copy(sB0, b0, 64);      stage_copy(sB1, b1, 64);
    int tid = threadIdx.x, lane = tid & 31, wid = tid >> 5;
    long long base = (long long)blockIdx.x * TILE;
    stage_conv(sT, base, N_NODES);
    __syncthreads();
    u64 h[32];
    init_bias(h, sB0, wid);
    layer_warp<64>(sT, sW0, h, lane, wid);
    relu32(h);
    __syncthreads();
    store_T(h, sT, lane, wid);
    __syncthreads();
    u64 acc[32];
    init_bias(acc, sB1, wid);
    layer_warp<64>(sT, sW1, acc, lane, wid);
    #pragma unroll
    for (int r = 0; r < 8; r++) {
        long long row = base + row_of(lane, r);
        if (row < N_NODES) {
            float4* o = (float4*)(g_h + row * 64 + wid * 8);
            float4 h0 = o[0], h1 = o[1];
            float2 a = upk(acc[r*4]), b = upk(acc[r*4+1]), c = upk(acc[r*4+2]), d = upk(acc[r*4+3]);
            o[0] = make_float4(fmaxf(h0.x + a.x, 0.f), fmaxf(h0.y + a.y, 0.f),
                               fmaxf(h0.z + b.x, 0.f), fmaxf(h0.w + b.y, 0.f));
            o[1] = make_float4(fmaxf(h1.x + c.x, 0.f), fmaxf(h1.y + c.y, 0.f),
                               fmaxf(h1.z + d.x, 0.f), fmaxf(h1.w + d.y, 0.f));
        }
    }
}

__global__ void __launch_bounds__(256, 2)
k_node_final(const int* __restrict__ batch,
             const float* __restrict__ w0, const float* __restrict__ b0,
             const float* __restrict__ w1, const float* __restrict__ b1,
             float* __restrict__ out) {
    extern __shared__ float smem[];
    float* sT  = smem;
    float* sW0 = sT + 64 * P1;
    float* sW1 = sW0 + 64 * 64;
    float* sB0 = sW1 + 64 * 64;
    float* sB1 = sB0 + 64;
    stage_copy(sW0, w0, 64 * 64); stage_copy(sW1, w1, 64 * 64);
    stage_copy(sB0, b0, 64);      stage_copy(sB1, b1, 64);
    int tid = threadIdx.x, lane = tid & 31, wid = tid >> 5;
    long long base = (long long)blockIdx.x * TILE;
    stage_conv(sT, base, N_NODES);
    __syncthreads();
    u64 h[32];
    init_bias(h, sB0, wid);
    layer_warp<64>(sT, sW0, h, lane, wid);
    relu32(h);
    __syncthreads();
    store_T(h, sT, lane, wid);
    __syncthreads();
    u64 acc[32];
    init_bias(acc, sB1, wid);
    layer_warp<64>(sT, sW1, acc, lane, wid);
    #pragma unroll
    for (int r = 0; r < 8; r++) {
        long long row = base + row_of(lane, r);
        if (row < N_NODES) {
            int bg = __ldg(&batch[row]);
            float* p = out + (size_t)bg * 64 + wid * 8;
            float2 a = upk(acc[r*4]), b = upk(acc[r*4+1]), c = upk(acc[r*4+2]), d = upk(acc[r*4+3]);
            red4(p,     a.x, a.y, b.x, b.y);
            red4(p + 4, c.x, c.y, d.x, d.y);
        }
    }
}

__global__ void k_zero_out(float4* out) {
    int i = blockIdx.x * 256 + threadIdx.x;
    out[i] = make_float4(0.f, 0.f, 0.f, 0.f);
}

// Gather (atomic-free, sequential e): 16 lanes per node.
__global__ void __launch_bounds__(256)
k_gather() {
    int gid = blockIdx.x * 256 + threadIdx.x;
    int n = gid >> 4, lane = gid & 15;
    if (n >= N_NODES) return;
    int beg = g_row[n], end = g_row[n + 1];
    float4 acc = make_float4(0.f, 0.f, 0.f, 0.f);
    for (int s = beg; s < end; s++) {
        int src = __ldg(&g_src[s]);
        float4 ev = __ldcs((const float4*)g_e + (size_t)s * 16 + lane);
        float4 hv = __ldg((const float4*)g_h + (size_t)src * 16 + lane);
        acc.x += fmaxf(hv.x + ev.x, 0.f);
        acc.y += fmaxf(hv.y + ev.y, 0.f);
        acc.z += fmaxf(hv.z + ev.z, 0.f);
        acc.w += fmaxf(hv.w + ev.w, 0.f);
    }
    ((float4*)g_agg)[(size_t)n * 16 + lane] = acc;
}

extern "C" void kernel_launch(void* const* d_in, const int* in_sizes, int n_in,
                              void* d_out, int out_size) {
    const float* x   = (const float*)d_in[0];
    const int*   ei  = (const int*)d_in[1];
    const float* ea  = (const float*)d_in[2];
    const int*   bat = (const int*)d_in[3];
    const float* wn0 = (const float*)d_in[4],  *bn0 = (const float*)d_in[5];
    const float* wn1 = (const float*)d_in[6],  *bn1 = (const float*)d_in[7];
    const float* we0 = (const float*)d_in[8],  *be0 = (const float*)d_in[9];
    const float* we1 = (const float*)d_in[10], *be1 = (const float*)d_in[11];
    const float* cw0 = (const float*)d_in[12], *cb0 = (const float*)d_in[13];
    const float* cw1 = (const float*)d_in[14], *cb1 = (const float*)d_in[15];
    const float* lw0 = (const float*)d_in[16], *lb0 = (const float*)d_in[17];
    const float* lw1 = (const float*)d_in[18], *lb1 = (const float*)d_in[19];
    float* out = (float*)d_out;

    const int SM_NODE = (64 * P1 + 32 * 64 + 64 * 64 + 128) * 4;
    const int SM_EDGE = (64 * P1 + 16 * 64 + 64 * 64 + 128) * 4;
    const int SM_CONV = (64 * P1 + 64 * 64 + 64 * 64 + 128) * 4;
    cudaFuncSetAttribute(k_node_init,   cudaFuncAttributeMaxDynamicSharedMemorySize, SM_NODE);
    cudaFuncSetAttribute(k_edge_init,   cudaFuncAttributeMaxDynamicSharedMemorySize, SM_EDGE);
    cudaFuncSetAttribute(k_node_update, cudaFuncAttributeMaxDynamicSharedMemorySize, SM_CONV);
    cudaFuncSetAttribute(k_node_final,  cudaFuncAttributeMaxDynamicSharedMemorySize, SM_CONV);

    const int E256       = (N_EDGES + 255) / 256;
    const int NODE_TILES = (N_NODES + TILE - 1) / TILE;   // 391
    const int EDGE_TILES = (N_EDGES + TILE - 1) / TILE;   // 3907
    const int GATH_BLOCKS = (N_NODES * 16 + 255) / 256;

    // launch index 3 = k_node_init (the slot ncu captures)
    k_zero_row<<<(N_NODES + 1 + 255) / 256, 256>>>();                       // 0
    k_count<<<E256, 256>>>(ei);                                              // 1
    k_scan<<<1, 1024>>>();                                                   // 2
    k_node_init<<<NODE_TILES, 256, SM_NODE>>>(x, wn0, bn0, wn1, bn1);        // 3 <- profiled
    k_fill<<<E256, 256>>>(ei);                                               // 4
    k_edge_init<<<EDGE_TILES, 256, SM_EDGE>>>(ea, we0, be0, we1, be1);       // 5
    k_zero_out<<<(N_GRAPHS * 64 / 4) / 256, 256>>>((float4*)out);            // 6

    for (int l = 0; l < 3; l++) {
        k_gather<<<GATH_BLOCKS, 256>>>();
        k_node_update<<<NODE_TILES, 256, SM_CONV>>>(cw0 + l * 64 * 64, cb0 + l * 64,
                                                    cw1 + l * 64 * 64, cb1 + l * 64);
    }
    k_gather<<<GATH_BLOCKS, 256>>>();
    k_node_final<<<NODE_TILES, 256, SM_CONV>>>(bat, lw0, lb0, lw1, lb1, out);
}

// round 12
// speedup vs baseline: 1.2613x; 1.0630x over previous
#include <cuda_runtime.h>

#define N_NODES 100000
#define N_EDGES 1000000
#define N_GRAPHS 512

#define TILE 128            // rows per block
#define P1   132            // transposed-tile pitch (floats)

typedef unsigned long long u64;

// Scratch (device globals — no allocation allowed)
__device__ float g_h[N_NODES * 64];     // node features   (25.6 MB)
__device__ float g_agg[N_NODES * 64];   // gather target   (25.6 MB)
__device__ float g_e[N_EDGES * 64];     // edge embeddings, CSR-permuted (256 MB)
__device__ int   g_row[N_NODES + 1];    // CSR row offsets (by dst)
__device__ int   g_cur[N_NODES];        // fill cursors
__device__ int   g_src[N_EDGES];        // src node per CSR slot
__device__ int   g_pos[N_EDGES];        // edge id -> CSR slot

// ---------------- packed f32x2 helpers (sm_100+) ----------------
__device__ __forceinline__ u64 pk2(float x) {
    u64 r; asm("mov.b64 %0, {%1, %1};" : "=l"(r) : "f"(x)); return r;
}
__device__ __forceinline__ u64 pk(float x, float y) {
    u64 r; asm("mov.b64 %0, {%1, %2};" : "=l"(r) : "f"(x), "f"(y)); return r;
}
__device__ __forceinline__ float2 upk(u64 v) {
    float2 f; asm("mov.b64 {%0, %1}, %2;" : "=f"(f.x), "=f"(f.y) : "l"(v)); return f;
}
__device__ __forceinline__ u64 ffma2(u64 a, u64 b, u64 c) {
    u64 d; asm("fma.rn.f32x2 %0, %1, %2, %3;" : "=l"(d) : "l"(a), "l"(b), "l"(c)); return d;
}
__device__ __forceinline__ void red4(float* p, float x, float y, float z, float w) {
    asm volatile("red.global.add.v4.f32 [%0], {%1, %2, %3, %4};"
                 :: "l"(p), "f"(x), "f"(y), "f"(z), "f"(w) : "memory");
}

// ================= tile core =================
// Block: 256 threads = 8 warps, tile 128 rows x 64 cols.
// Warp wid owns col-block [wid*8, wid*8+8): W loads warp-BROADCAST (1 wf each).
// Lane owns rows lane*4..+4: A load = one lane-consecutive LDS.128 (4 wf).
// acc[r*4+j]: row lane*4+r, col-pair (wid*8+2j, +1) as f32x2.  16 acc regs.

template<int K>
__device__ __forceinline__ void layer_warp(const float* sT, const float* sW,
                                           u64* acc, int lane, int wid) {
    const float* aB = sT + lane * 4;
    const float* wB = sW + wid * 8;
    #pragma unroll 2
    for (int k = 0; k < K; k++) {
        float4 a = *(const float4*)(aB + k * P1);
        const ulonglong2* wP = (const ulonglong2*)(wB + k * 64);
        ulonglong2 wA = wP[0], wBv = wP[1];
        u64 w[4] = { wA.x, wA.y, wBv.x, wBv.y };
        float ar[4] = { a.x, a.y, a.z, a.w };
        #pragma unroll
        for (int r = 0; r < 4; r++) {
            u64 av = pk2(ar[r]);
            #pragma unroll
            for (int j = 0; j < 4; j++) acc[r * 4 + j] = ffma2(av, w[j], acc[r * 4 + j]);
        }
    }
}

__device__ __forceinline__ void init_bias(u64* acc, const float* sB, int wid) {
    const u64* b = (const u64*)sB;
    u64 bv[4];
    #pragma unroll
    for (int j = 0; j < 4; j++) bv[j] = b[wid * 4 + j];   // broadcast
    #pragma unroll
    for (int r = 0; r < 4; r++)
        #pragma unroll
        for (int j = 0; j < 4; j++) acc[r * 4 + j] = bv[j];
}

__device__ __forceinline__ void relu16(u64* h) {
    #pragma unroll
    for (int i = 0; i < 16; i++) {
        float2 f = upk(h[i]);
        h[i] = pk(fmaxf(f.x, 0.f), fmaxf(f.y, 0.f));
    }
}

// transpose-store thread's 4 rows x 8 cols into sT[col][row]; all lanes of a
// warp write the same column -> lane-consecutive STS.128, conflict-free
__device__ __forceinline__ void store_T(const u64* h, float* sT, int lane, int wid) {
    #pragma unroll
    for (int c = 0; c < 8; c++) {
        int gc = wid * 8 + c, j = c >> 1;
        float g0[4];
        if (c & 1) {
            #pragma unroll
            for (int r = 0; r < 4; r++) g0[r] = upk(h[r*4+j]).y;
        } else {
            #pragma unroll
            for (int r = 0; r < 4; r++) g0[r] = upk(h[r*4+j]).x;
        }
        *(float4*)(sT + gc * P1 + lane * 4) = make_float4(g0[0], g0[1], g0[2], g0[3]);
    }
}

__device__ __forceinline__ void stage_copy(float* dst, const float* __restrict__ src, int n) {
    for (int i = threadIdx.x; i < n; i += 256) dst[i] = src[i];
}

// ---------------- CSR construction ----------------
__global__ void k_zero_row() {
    int i = blockIdx.x * 256 + threadIdx.x;
    if (i <= N_NODES) g_row[i] = 0;
}

__global__ void k_count(const int* __restrict__ ei) {
    int e = blockIdx.x * 256 + threadIdx.x;
    if (e < N_EDGES) atomicAdd(&g_row[ei[N_EDGES + e]], 1);
}

__global__ void __launch_bounds__(1024) k_scan() {
    __shared__ int warp_tot[32];
    __shared__ int carry_s, tot_s;
    int tid = threadIdx.x, lane = tid & 31, wid = tid >> 5;
    if (tid == 0) carry_s = 0;
    __syncthreads();
    for (int base = 0; base < N_NODES; base += 4096) {
        int idx = base + tid * 4;
        int v0 = (idx     < N_NODES) ? g_row[idx]     : 0;
        int v1 = (idx + 1 < N_NODES) ? g_row[idx + 1] : 0;
        int v2 = (idx + 2 < N_NODES) ? g_row[idx + 2] : 0;
        int v3 = (idx + 3 < N_NODES) ? g_row[idx + 3] : 0;
        int s0 = v0, s1 = s0 + v1, s2 = s1 + v2, s3 = s2 + v3;
        int tsum = s3;
        int incl = tsum;
        #pragma unroll
        for (int off = 1; off < 32; off <<= 1) {
            int t = __shfl_up_sync(0xffffffff, incl, off);
            if (lane >= off) incl += t;
        }
        if (lane == 31) warp_tot[wid] = incl;
        __syncthreads();
        if (wid == 0) {
            int w = warp_tot[lane];
            int wi = w;
            #pragma unroll
            for (int off = 1; off < 32; off <<= 1) {
                int t = __shfl_up_sync(0xffffffff, wi, off);
                if (lane >= off) wi += t;
            }
            warp_tot[lane] = wi - w;
            if (lane == 31) tot_s = wi;
        }
        __syncthreads();
        int eb = carry_s + warp_tot[wid] + (incl - tsum);
        if (idx     < N_NODES) { g_row[idx]     = eb;      g_cur[idx]     = eb; }
        if (idx + 1 < N_NODES) { g_row[idx + 1] = eb + s0; g_cur[idx + 1] = eb + s0; }
        if (idx + 2 < N_NODES) { g_row[idx + 2] = eb + s1; g_cur[idx + 2] = eb + s1; }
        if (idx + 3 < N_NODES) { g_row[idx + 3] = eb + s2; g_cur[idx + 3] = eb + s2; }
        __syncthreads();
        if (tid == 0) carry_s += tot_s;
        __syncthreads();
    }
    if (tid == 0) g_row[N_NODES] = N_EDGES;
}

__global__ void k_fill(const int* __restrict__ ei) {
    int e = blockIdx.x * 256 + threadIdx.x;
    if (e >= N_EDGES) return;
    int src = ei[e];
    int dst = ei[N_EDGES + e];
    int p = atomicAdd(&g_cur[dst], 1);
    g_src[p] = src;
    g_pos[e] = p;
}

// ---------------- MLP kernels ----------------
// smem: [sT 64*P1 | sW0 KIN*64 | sW1 64*64 | b0 64 | b1 64]

__global__ void __launch_bounds__(256, 3)
k_node_init(const float* __restrict__ x,
            const float* __restrict__ w0, const float* __restrict__ b0,
            const float* __restrict__ w1, const float* __restrict__ b1) {
    extern __shared__ float smem[];
    float* sT  = smem;
    float* sW0 = sT + 64 * P1;
    float* sW1 = sW0 + 32 * 64;
    float* sB0 = sW1 + 64 * 64;
    float* sB1 = sB0 + 64;
    stage_copy(sW0, w0, 32 * 64); stage_copy(sW1, w1, 64 * 64);
    stage_copy(sB0, b0, 64);      stage_copy(sB1, b1, 64);
    int tid = threadIdx.x, lane = tid & 31, wid = tid >> 5;
    long long base = (long long)blockIdx.x * TILE;
    for (int i = tid; i < TILE * 8; i += 256) {
        int row = i >> 3, k4 = i & 7;
        long long gr = base + row; if (gr >= N_NODES) gr = N_NODES - 1;
        float4 v = ((const float4*)(x + gr * 32))[k4];
        int k = k4 * 4;
        sT[(k + 0) * P1 + row] = v.x;
        sT[(k + 1) * P1 + row] = v.y;
        sT[(k + 2) * P1 + row] = v.z;
        sT[(k + 3) * P1 + row] = v.w;
    }
    __syncthreads();
    u64 h[16];
    init_bias(h, sB0, wid);
    layer_warp<32>(sT, sW0, h, lane, wid);
    relu16(h);
    __syncthreads();
    store_T(h, sT, lane, wid);
    __syncthreads();
    u64 acc[16];
    init_bias(acc, sB1, wid);
    layer_warp<64>(sT, sW1, acc, lane, wid);
    #pragma unroll
    for (int r = 0; r < 4; r++) {
        long long row = base + lane * 4 + r;
        if (row < N_NODES) {
            float2 a = upk(acc[r*4]), b = upk(acc[r*4+1]), c = upk(acc[r*4+2]), d = upk(acc[r*4+3]);
            float4* o = (float4*)(g_h + row * 64 + wid * 8);
            o[0] = make_float4(a.x, a.y, b.x, b.y);
            o[1] = make_float4(c.x, c.y, d.x, d.y);
        }
    }
}

__global__ void __launch_bounds__(256, 3)
k_edge_init(const float* __restrict__ ea,
            const float* __restrict__ w0, const float* __restrict__ b0,
            const float* __restrict__ w1, const float* __restrict__ b1) {
    extern __shared__ float smem[];
    float* sT  = smem;
    float* sW0 = sT + 64 * P1;
    float* sW1 = sW0 + 16 * 64;
    float* sB0 = sW1 + 64 * 64;
    float* sB1 = sB0 + 64;
    stage_copy(sW0, w0, 16 * 64); stage_copy(sW1, w1, 64 * 64);
    stage_copy(sB0, b0, 64);      stage_copy(sB1, b1, 64);
    int tid = threadIdx.x, lane = tid & 31, wid = tid >> 5;
    long long base = (long long)blockIdx.x * TILE;
    for (int i = tid; i < TILE * 4; i += 256) {
        int row = i >> 2, k4 = i & 3;
        long long gr = base + row; if (gr >= N_EDGES) gr = N_EDGES - 1;
        float4 v = ((const float4*)(ea + gr * 16))[k4];
        int k = k4 * 4;
        sT[(k + 0) * P1 + row] = v.x;
        sT[(k + 1) * P1 + row] = v.y;
        sT[(k + 2) * P1 + row] = v.z;
        sT[(k + 3) * P1 + row] = v.w;
    }
    __syncthreads();
    u64 h[16];
    init_bias(h, sB0, wid);
    layer_warp<16>(sT, sW0, h, lane, wid);
    relu16(h);
    __syncthreads();
    store_T(h, sT, lane, wid);
    __syncthreads();
    u64 acc[16];
    init_bias(acc, sB1, wid);
    layer_warp<64>(sT, sW1, acc, lane, wid);
    #pragma unroll
    for (int r = 0; r < 4; r++) {
        long long row = base + lane * 4 + r;
        if (row < N_EDGES) {
            int p = __ldg(&g_pos[row]);
            float2 a = upk(acc[r*4]), b = upk(acc[r*4+1]), c = upk(acc[r*4+2]), d = upk(acc[r*4+3]);
            float4* o = (float4*)(g_e + (size_t)p * 64 + wid * 8);
            __stcs(&o[0], make_float4(a.x, a.y, b.x, b.y));
            __stcs(&o[1], make_float4(c.x, c.y, d.x, d.y));
        }
    }
}

// conv staging: t = agg + 1.1*h, transposed
__device__ __forceinline__ void stage_conv(float* sT, long long base, long long limit) {
    for (int i = threadIdx.x; i < TILE * 16; i += 256) {
        int row = i >> 4, k4 = i & 15;
        long long gr = base + row; if (gr >= limit) gr = limit - 1;
        float4 a = ((const float4*)(g_agg + gr * 64))[k4];
        float4 h = ((const float4*)(g_h   + gr * 64))[k4];
        int k = k4 * 4;
        sT[(k + 0) * P1 + row] = fmaf(1.1f, h.x, a.x);
        sT[(k + 1) * P1 + row] = fmaf(1.1f, h.y, a.y);
        sT[(k + 2) * P1 + row] = fmaf(1.1f, h.z, a.z);
        sT[(k + 3) * P1 + row] = fmaf(1.1f, h.w, a.w);
    }
}

__global__ void __launch_bounds__(256, 3)
k_node_update(const float* __restrict__ w0, const float* __restrict__ b0,
              const float* __restrict__ w1, const float* __restrict__ b1) {
    extern __shared__ float smem[];
    float* sT  = smem;
    float* sW0 = sT + 64 * P1;
    float* sW1 = sW0 + 64 * 64;
    float* sB0 = sW1 + 64 * 64;
    float* sB1 = sB0 + 64;
    stage_copy(sW0, w0, 64 * 64); stage_copy(sW1, w1, 64 * 64);
    stage_copy(sB0, b0, 64);      stage_copy(sB1, b1, 64);
    int tid = threadIdx.x, lane = tid & 31, wid = tid >> 5;
    long long base = (long long)blockIdx.x * TILE;
    stage_conv(sT, base, N_NODES);
    __syncthreads();
    u64 h[16];
    init_bias(h, sB0, wid);
    layer_warp<64>(sT, sW0, h, lane, wid);
    relu16(h);
    __syncthreads();
    store_T(h, sT, lane, wid);
    __syncthreads();
    u64 acc[16];
    init_bias(acc, sB1, wid);
    layer_warp<64>(sT, sW1, acc, lane, wid);
    #pragma unroll
    for (int r = 0; r < 4; r++) {
        long long row = base + lane * 4 + r;
        if (row < N_NODES) {
            float4* o = (float4*)(g_h + row * 64 + wid * 8);
            float4 h0 = o[0], h1 = o[1];
            float2 a = upk(acc[r*4]), b = upk(acc[r*4+1]), c = upk(acc[r*4+2]), d = upk(acc[r*4+3]);
            o[0] = make_float4(fmaxf(h0.x + a.x, 0.f), fmaxf(h0.y + a.y, 0.f),
                               fmaxf(h0.z + b.x, 0.f), fmaxf(h0.w + b.y, 0.f));
            o[1] = make_float4(fmaxf(h1.x + c.x, 0.f), fmaxf(h1.y + c.y, 0.f),
                               fmaxf(h1.z + d.x, 0.f), fmaxf(h1.w + d.y, 0.f));
        }
    }
}

__global__ void __launch_bounds__(256, 3)
k_node_final(const int* __restrict__ batch,
             const float* __restrict__ w0, const float* __restrict__ b0,
             const float* __restrict__ w1, const float* __restrict__ b1,
             float* __restrict__ out) {
    extern __shared__ float smem[];
    float* sT  = smem;
    float* sW0 = sT + 64 * P1;
    float* sW1 = sW0 + 64 * 64;
    float* sB0 = sW1 + 64 * 64;
    float* sB1 = sB0 + 64;
    stage_copy(sW0, w0, 64 * 64); stage_copy(sW1, w1, 64 * 64);
    stage_copy(sB0, b0, 64);      stage_copy(sB1, b1, 64);
    int tid = threadIdx.x, lane = tid & 31, wid = tid >> 5;
    long long base = (long long)blockIdx.x * TILE;
    stage_conv(sT, base, N_NODES);
    __syncthreads();
    u64 h[16];
    init_bias(h, sB0, wid);
    layer_warp<64>(sT, sW0, h, lane, wid);
    relu16(h);
    __syncthreads();
    store_T(h, sT, lane, wid);
    __syncthreads();
    u64 acc[16];
    init_bias(acc, sB1, wid);
    layer_warp<64>(sT, sW1, acc, lane, wid);
    #pragma unroll
    for (int r = 0; r < 4; r++) {
        long long row = base + lane * 4 + r;
        if (row < N_NODES) {
            int bg = __ldg(&batch[row]);
            float* p = out + (size_t)bg * 64 + wid * 8;
            float2 a = upk(acc[r*4]), b = upk(acc[r*4+1]), c = upk(acc[r*4+2]), d = upk(acc[r*4+3]);
            red4(p,     a.x, a.y, b.x, b.y);
            red4(p + 4, c.x, c.y, d.x, d.y);
        }
    }
}

__global__ void k_zero_out(float4* out) {
    int i = blockIdx.x * 256 + threadIdx.x;
    out[i] = make_float4(0.f, 0.f, 0.f, 0.f);
}

// Gather (atomic-free, sequential e): 16 lanes per node.
__global__ void __launch_bounds__(256)
k_gather() {
    int gid = blockIdx.x * 256 + threadIdx.x;
    int n = gid >> 4, lane = gid & 15;
    if (n >= N_NODES) return;
    int beg = g_row[n], end = g_row[n + 1];
    float4 acc = make_float4(0.f, 0.f, 0.f, 0.f);
    for (int s = beg; s < end; s++) {
        int src = __ldg(&g_src[s]);
        float4 ev = __ldcs((const float4*)g_e + (size_t)s * 16 + lane);
        float4 hv = __ldg((const float4*)g_h + (size_t)src * 16 + lane);
        acc.x += fmaxf(hv.x + ev.x, 0.f);
        acc.y += fmaxf(hv.y + ev.y, 0.f);
        acc.z += fmaxf(hv.z + ev.z, 0.f);
        acc.w += fmaxf(hv.w + ev.w, 0.f);
    }
    ((float4*)g_agg)[(size_t)n * 16 + lane] = acc;
}

extern "C" void kernel_launch(void* const* d_in, const int* in_sizes, int n_in,
                              void* d_out, int out_size) {
    const float* x   = (const float*)d_in[0];
    const int*   ei  = (const int*)d_in[1];
    const float* ea  = (const float*)d_in[2];
    const int*   bat = (const int*)d_in[3];
    const float* wn0 = (const float*)d_in[4],  *bn0 = (const float*)d_in[5];
    const float* wn1 = (const float*)d_in[6],  *bn1 = (const float*)d_in[7];
    const float* we0 = (const float*)d_in[8],  *be0 = (const float*)d_in[9];
    const float* we1 = (const float*)d_in[10], *be1 = (const float*)d_in[11];
    const float* cw0 = (const float*)d_in[12], *cb0 = (const float*)d_in[13];
    const float* cw1 = (const float*)d_in[14], *cb1 = (const float*)d_in[15];
    const float* lw0 = (const float*)d_in[16], *lb0 = (const float*)d_in[17];
    const float* lw1 = (const float*)d_in[18], *lb1 = (const float*)d_in[19];
    float* out = (float*)d_out;

    const int SM_NODE = (64 * P1 + 32 * 64 + 64 * 64 + 128) * 4;
    const int SM_EDGE = (64 * P1 + 16 * 64 + 64 * 64 + 128) * 4;
    const int SM_CONV = (64 * P1 + 64 * 64 + 64 * 64 + 128) * 4;
    cudaFuncSetAttribute(k_node_init,   cudaFuncAttributeMaxDynamicSharedMemorySize, SM_NODE);
    cudaFuncSetAttribute(k_edge_init,   cudaFuncAttributeMaxDynamicSharedMemorySize, SM_EDGE);
    cudaFuncSetAttribute(k_node_update, cudaFuncAttributeMaxDynamicSharedMemorySize, SM_CONV);
    cudaFuncSetAttribute(k_node_final,  cudaFuncAttributeMaxDynamicSharedMemorySize, SM_CONV);

    const int E256       = (N_EDGES + 255) / 256;
    const int NODE_TILES = (N_NODES + TILE - 1) / TILE;   // 782
    const int EDGE_TILES = (N_EDGES + TILE - 1) / TILE;   // 7813
    const int GATH_BLOCKS = (N_NODES * 16 + 255) / 256;

    // launch index 3 = k_node_init (the slot ncu captures)
    k_zero_row<<<(N_NODES + 1 + 255) / 256, 256>>>();                       // 0
    k_count<<<E256, 256>>>(ei);                                              // 1
    k_scan<<<1, 1024>>>();                                                   // 2
    k_node_init<<<NODE_TILES, 256, SM_NODE>>>(x, wn0, bn0, wn1, bn1);        // 3 <- profiled
    k_fill<<<E256, 256>>>(ei);                                               // 4
    k_edge_init<<<EDGE_TILES, 256, SM_EDGE>>>(ea, we0, be0, we1, be1);       // 5
    k_zero_out<<<(N_GRAPHS * 64 / 4) / 256, 256>>>((float4*)out);            // 6

    for (int l = 0; l < 3; l++) {
        k_gather<<<GATH_BLOCKS, 256>>>();
        k_node_update<<<NODE_TILES, 256, SM_CONV>>>(cw0 + l * 64 * 64, cb0 + l * 64,
                                                    cw1 + l * 64 * 64, cb1 + l * 64);
    }
    k_gather<<<GATH_BLOCKS, 256>>>();
    k_node_final<<<NODE_TILES, 256, SM_CONV>>>(bat, lw0, lb0, lw1, lb1, out);
}

// round 13
// speedup vs baseline: 1.7340x; 1.3748x over previous
#include <cuda_runtime.h>
#include <cuda_bf16.h>

#define N_NODES 100000
#define N_EDGES 1000000
#define N_GRAPHS 512

#define TILE 128           // rows per block
#define PB   72            // bf16 tile pitch (144B rows -> conflict-free LDSM)

typedef unsigned int u32;

// Scratch (device globals — no allocation allowed)
__device__ float g_h[N_NODES * 64];     // node features   (25.6 MB)
__device__ float g_agg[N_NODES * 64];   // gather target   (25.6 MB)
__device__ float g_e[N_EDGES * 64];     // edge embeddings, CSR-permuted (256 MB)
__device__ int   g_row[N_NODES + 1];    // CSR row offsets (by dst)
__device__ int   g_cur[N_NODES];        // fill cursors
__device__ int   g_src[N_EDGES];        // src node per CSR slot
__device__ int   g_pos[N_EDGES];        // edge id -> CSR slot

// ---------------- PTX helpers ----------------
__device__ __forceinline__ u32 su32(const void* p) {
    return (u32)__cvta_generic_to_shared(p);
}
__device__ __forceinline__ void ldsm_x4(u32* r, u32 addr) {
    asm volatile("ldmatrix.sync.aligned.m8n8.x4.shared.b16 {%0,%1,%2,%3}, [%4];"
                 : "=r"(r[0]), "=r"(r[1]), "=r"(r[2]), "=r"(r[3]) : "r"(addr));
}
__device__ __forceinline__ void ldsm_x2t(u32* r, u32 addr) {
    asm volatile("ldmatrix.sync.aligned.m8n8.x2.trans.shared.b16 {%0,%1}, [%2];"
                 : "=r"(r[0]), "=r"(r[1]) : "r"(addr));
}
__device__ __forceinline__ void mma_bf16(float* d, const u32* a, const u32* b) {
    asm volatile("mma.sync.aligned.m16n8k16.row.col.f32.bf16.bf16.f32 "
                 "{%0,%1,%2,%3}, {%4,%5,%6,%7}, {%8,%9}, {%0,%1,%2,%3};"
                 : "+f"(d[0]), "+f"(d[1]), "+f"(d[2]), "+f"(d[3])
                 : "r"(a[0]), "r"(a[1]), "r"(a[2]), "r"(a[3]), "r"(b[0]), "r"(b[1]));
}
__device__ __forceinline__ void red2(float* p, float x, float y) {
    asm volatile("red.global.add.v2.f32 [%0], {%1,%2};" :: "l"(p), "f"(x), "f"(y) : "memory");
}

// split a float pair into hi/lo bf16 pairs (error compensation)
__device__ __forceinline__ void splitp(float v0, float v1,
                                       __nv_bfloat162& hi, __nv_bfloat162& lo) {
    __nv_bfloat16 h0 = __float2bfloat16(v0);
    __nv_bfloat16 h1 = __float2bfloat16(v1);
    __nv_bfloat16 l0 = __float2bfloat16(v0 - __bfloat162float(h0));
    __nv_bfloat16 l1 = __float2bfloat16(v1 - __bfloat162float(h1));
    hi = __halves2bfloat162(h0, h1);
    lo = __halves2bfloat162(l0, l1);
}

// ---------------- MMA MLP layer ----------------
// Block = 256 threads = 8 warps; warp w owns rows m0=w*16 .. +16, all 64 cols.
// A tiles (hi/lo) [128][PB] bf16 in smem; W tiles (hi/lo) [K][PB]; bias fp32.
// acc[nb][0..3] = D rows (lane/4, lane/4+8) x cols (nb*8+(lane%3)*2 .. +1).
template<int KSTEPS>
__device__ __forceinline__ void mma_layer(u32 aHiB, u32 aLoB, u32 wHiB, u32 wLoB,
                                          const float* sB, float acc[8][4],
                                          int lane, int m0) {
    int col0 = (lane & 3) * 2;
    #pragma unroll
    for (int nb = 0; nb < 8; nb++) {
        float b0 = sB[nb * 8 + col0], b1 = sB[nb * 8 + col0 + 1];
        acc[nb][0] = b0; acc[nb][1] = b1; acc[nb][2] = b0; acc[nb][3] = b1;
    }
    int arow = m0 + (lane & 15);
    int acol = (lane >> 4) * 8;
    #pragma unroll
    for (int ks = 0; ks < KSTEPS; ks++) {
        int k0 = ks * 16;
        u32 ah[4], al[4];
        ldsm_x4(ah, aHiB + (u32)((arow * PB + k0 + acol) * 2));
        ldsm_x4(al, aLoB + (u32)((arow * PB + k0 + acol) * 2));
        int brow = k0 + (lane & 15);
        #pragma unroll
        for (int nb = 0; nb < 8; nb++) {
            u32 bh[2], bl[2];
            ldsm_x2t(bh, wHiB + (u32)((brow * PB + nb * 8) * 2));
            ldsm_x2t(bl, wLoB + (u32)((brow * PB + nb * 8) * 2));
            mma_bf16(acc[nb], ah, bh);
            mma_bf16(acc[nb], ah, bl);
            mma_bf16(acc[nb], al, bh);
        }
    }
}

// relu + hi/lo split store of acc into A tiles (for layer2 input)
__device__ __forceinline__ void hidden_store(float acc[8][4],
                                             __nv_bfloat16* aHi, __nv_bfloat16* aLo,
                                             int lane, int m0) {
    int r0 = m0 + (lane >> 2), r1 = r0 + 8;
    int col0 = (lane & 3) * 2;
    #pragma unroll
    for (int nb = 0; nb < 8; nb++) {
        int c = nb * 8 + col0;
        float v0 = fmaxf(acc[nb][0], 0.f), v1 = fmaxf(acc[nb][1], 0.f);
        float v2 = fmaxf(acc[nb][2], 0.f), v3 = fmaxf(acc[nb][3], 0.f);
        __nv_bfloat162 h2, l2;
        splitp(v0, v1, h2, l2);
        *(__nv_bfloat162*)(aHi + r0 * PB + c) = h2;
        *(__nv_bfloat162*)(aLo + r0 * PB + c) = l2;
        splitp(v2, v3, h2, l2);
        *(__nv_bfloat162*)(aHi + r1 * PB + c) = h2;
        *(__nv_bfloat162*)(aLo + r1 * PB + c) = l2;
    }
}

// stage fp32 weights [K][64] as hi/lo bf16 tiles
__device__ __forceinline__ void stage_w(const float* __restrict__ w, int K,
                                        __nv_bfloat16* wHi, __nv_bfloat16* wLo) {
    for (int i = threadIdx.x; i < K * 32; i += 256) {
        int k = i >> 5, c2 = (i & 31) * 2;
        __nv_bfloat162 h2, l2;
        splitp(w[k * 64 + c2], w[k * 64 + c2 + 1], h2, l2);
        *(__nv_bfloat162*)(wHi + k * PB + c2) = h2;
        *(__nv_bfloat162*)(wLo + k * PB + c2) = l2;
    }
}
__device__ __forceinline__ void stage_b(const float* __restrict__ b, float* sB) {
    for (int i = threadIdx.x; i < 64; i += 256) sB[i] = b[i];
}

// ---------------- CSR construction ----------------
__global__ void k_zero_row() {
    int i = blockIdx.x * 256 + threadIdx.x;
    if (i <= N_NODES) g_row[i] = 0;
}

__global__ void k_count(const int* __restrict__ ei) {
    int e = blockIdx.x * 256 + threadIdx.x;
    if (e < N_EDGES) atomicAdd(&g_row[ei[N_EDGES + e]], 1);
}

__global__ void __launch_bounds__(1024) k_scan() {
    __shared__ int warp_tot[32];
    __shared__ int carry_s, tot_s;
    int tid = threadIdx.x, lane = tid & 31, wid = tid >> 5;
    if (tid == 0) carry_s = 0;
    __syncthreads();
    for (int base = 0; base < N_NODES; base += 4096) {
        int idx = base + tid * 4;
        int v0 = (idx     < N_NODES) ? g_row[idx]     : 0;
        int v1 = (idx + 1 < N_NODES) ? g_row[idx + 1] : 0;
        int v2 = (idx + 2 < N_NODES) ? g_row[idx + 2] : 0;
        int v3 = (idx + 3 < N_NODES) ? g_row[idx + 3] : 0;
        int s0 = v0, s1 = s0 + v1, s2 = s1 + v2, s3 = s2 + v3;
        int tsum = s3;
        int incl = tsum;
        #pragma unroll
        for (int off = 1; off < 32; off <<= 1) {
            int t = __shfl_up_sync(0xffffffff, incl, off);
            if (lane >= off) incl += t;
        }
        if (lane == 31) warp_tot[wid] = incl;
        __syncthreads();
        if (wid == 0) {
            int w = warp_tot[lane];
            int wi = w;
            #pragma unroll
            for (int off = 1; off < 32; off <<= 1) {
                int t = __shfl_up_sync(0xffffffff, wi, off);
                if (lane >= off) wi += t;
            }
            warp_tot[lane] = wi - w;
            if (lane == 31) tot_s = wi;
        }
        __syncthreads();
        int eb = carry_s + warp_tot[wid] + (incl - tsum);
        if (idx     < N_NODES) { g_row[idx]     = eb;      g_cur[idx]     = eb; }
        if (idx + 1 < N_NODES) { g_row[idx + 1] = eb + s0; g_cur[idx + 1] = eb + s0; }
        if (idx + 2 < N_NODES) { g_row[idx + 2] = eb + s1; g_cur[idx + 2] = eb + s1; }
        if (idx + 3 < N_NODES) { g_row[idx + 3] = eb + s2; g_cur[idx + 3] = eb + s2; }
        __syncthreads();
        if (tid == 0) carry_s += tot_s;
        __syncthreads();
    }
    if (tid == 0) g_row[N_NODES] = N_EDGES;
}

__global__ void k_fill(const int* __restrict__ ei) {
    int e = blockIdx.x * 256 + threadIdx.x;
    if (e >= N_EDGES) return;
    int src = ei[e];
    int dst = ei[N_EDGES + e];
    int p = atomicAdd(&g_cur[dst], 1);
    g_src[p] = src;
    g_pos[e] = p;
}

// ---------------- MLP kernels (tensor-core) ----------------
// smem bytes: aHi|aLo [128*PB]x2, w0Hi|w0Lo [KIN*PB]x2, w1Hi|w1Lo [64*PB]x2, b0,b1

__global__ void __launch_bounds__(256, 2)
k_node_init(const float* __restrict__ x,
            const float* __restrict__ w0, const float* __restrict__ b0,
            const float* __restrict__ w1, const float* __restrict__ b1) {
    extern __shared__ char sm[];
    __nv_bfloat16* aHi = (__nv_bfloat16*)sm;
    __nv_bfloat16* aLo = aHi + 128 * PB;
    __nv_bfloat16* w0H = aLo + 128 * PB;
    __nv_bfloat16* w0L = w0H + 32 * PB;
    __nv_bfloat16* w1H = w0L + 32 * PB;
    __nv_bfloat16* w1L = w1H + 64 * PB;
    float* sB0 = (float*)(w1L + 64 * PB);
    float* sB1 = sB0 + 64;
    stage_w(w0, 32, w0H, w0L); stage_w(w1, 64, w1H, w1L);
    stage_b(b0, sB0); stage_b(b1, sB1);
    int tid = threadIdx.x, lane = tid & 31, wid = tid >> 5, m0 = wid * 16;
    long long base = (long long)blockIdx.x * TILE;
    for (int i = tid; i < TILE * 8; i += 256) {
        int row = i >> 3, q = i & 7;
        long long gr = base + row; if (gr >= N_NODES) gr = N_NODES - 1;
        float4 v = ((const float4*)(x + gr * 32))[q];
        __nv_bfloat162 h2, l2;
        splitp(v.x, v.y, h2, l2);
        *(__nv_bfloat162*)(aHi + row * PB + q * 4) = h2;
        *(__nv_bfloat162*)(aLo + row * PB + q * 4) = l2;
        splitp(v.z, v.w, h2, l2);
        *(__nv_bfloat162*)(aHi + row * PB + q * 4 + 2) = h2;
        *(__nv_bfloat162*)(aLo + row * PB + q * 4 + 2) = l2;
    }
    __syncthreads();
    u32 aHiB = su32(aHi), aLoB = su32(aLo);
    float acc[8][4];
    mma_layer<2>(aHiB, aLoB, su32(w0H), su32(w0L), sB0, acc, lane, m0);
    __syncthreads();
    hidden_store(acc, aHi, aLo, lane, m0);
    __syncthreads();
    mma_layer<4>(aHiB, aLoB, su32(w1H), su32(w1L), sB1, acc, lane, m0);
    int r0 = m0 + (lane >> 2), col0 = (lane & 3) * 2;
    long long row0 = base + r0, row1 = row0 + 8;
    #pragma unroll
    for (int nb = 0; nb < 8; nb++) {
        int c = nb * 8 + col0;
        if (row0 < N_NODES) *(float2*)(g_h + row0 * 64 + c) = make_float2(acc[nb][0], acc[nb][1]);
        if (row1 < N_NODES) *(float2*)(g_h + row1 * 64 + c) = make_float2(acc[nb][2], acc[nb][3]);
    }
}

__global__ void __launch_bounds__(256, 2)
k_edge_init(const float* __restrict__ ea,
            const float* __restrict__ w0, const float* __restrict__ b0,
            const float* __restrict__ w1, const float* __restrict__ b1) {
    extern __shared__ char sm[];
    __nv_bfloat16* aHi = (__nv_bfloat16*)sm;
    __nv_bfloat16* aLo = aHi + 128 * PB;
    __nv_bfloat16* w0H = aLo + 128 * PB;
    __nv_bfloat16* w0L = w0H + 16 * PB;
    __nv_bfloat16* w1H = w0L + 16 * PB;
    __nv_bfloat16* w1L = w1H + 64 * PB;
    float* sB0 = (float*)(w1L + 64 * PB);
    float* sB1 = sB0 + 64;
    stage_w(w0, 16, w0H, w0L); stage_w(w1, 64, w1H, w1L);
    stage_b(b0, sB0); stage_b(b1, sB1);
    int tid = threadIdx.x, lane = tid & 31, wid = tid >> 5, m0 = wid * 16;
    long long base = (long long)blockIdx.x * TILE;
    for (int i = tid; i < TILE * 4; i += 256) {
        int row = i >> 2, q = i & 3;
        long long gr = base + row; if (gr >= N_EDGES) gr = N_EDGES - 1;
        float4 v = ((const float4*)(ea + gr * 16))[q];
        __nv_bfloat162 h2, l2;
        splitp(v.x, v.y, h2, l2);
        *(__nv_bfloat162*)(aHi + row * PB + q * 4) = h2;
        *(__nv_bfloat162*)(aLo + row * PB + q * 4) = l2;
        splitp(v.z, v.w, h2, l2);
        *(__nv_bfloat162*)(aHi + row * PB + q * 4 + 2) = h2;
        *(__nv_bfloat162*)(aLo + row * PB + q * 4 + 2) = l2;
    }
    __syncthreads();
    u32 aHiB = su32(aHi), aLoB = su32(aLo);
    float acc[8][4];
    mma_layer<1>(aHiB, aLoB, su32(w0H), su32(w0L), sB0, acc, lane, m0);
    __syncthreads();
    hidden_store(acc, aHi, aLo, lane, m0);
    __syncthreads();
    mma_layer<4>(aHiB, aLoB, su32(w1H), su32(w1L), sB1, acc, lane, m0);
    int r0 = m0 + (lane >> 2), col0 = (lane & 3) * 2;
    long long row0 = base + r0, row1 = row0 + 8;
    int p0 = 0, p1 = 0;
    if (row0 < N_EDGES) p0 = __ldg(&g_pos[row0]);
    if (row1 < N_EDGES) p1 = __ldg(&g_pos[row1]);
    #pragma unroll
    for (int nb = 0; nb < 8; nb++) {
        int c = nb * 8 + col0;
        if (row0 < N_EDGES) __stcs((float2*)(g_e + (size_t)p0 * 64 + c), make_float2(acc[nb][0], acc[nb][1]));
        if (row1 < N_EDGES) __stcs((float2*)(g_e + (size_t)p1 * 64 + c), make_float2(acc[nb][2], acc[nb][3]));
    }
}

// conv staging: t = agg + 1.1*h, hi/lo split
__device__ __forceinline__ void stage_conv(__nv_bfloat16* aHi, __nv_bfloat16* aLo,
                                           long long base, long long limit) {
    for (int i = threadIdx.x; i < TILE * 16; i += 256) {
        int row = i >> 4, k4 = i & 15;
        long long gr = base + row; if (gr >= limit) gr = limit - 1;
        float4 a = ((const float4*)(g_agg + gr * 64))[k4];
        float4 h = ((const float4*)(g_h   + gr * 64))[k4];
        float t0 = fmaf(1.1f, h.x, a.x), t1 = fmaf(1.1f, h.y, a.y);
        float t2 = fmaf(1.1f, h.z, a.z), t3 = fmaf(1.1f, h.w, a.w);
        __nv_bfloat162 h2, l2;
        splitp(t0, t1, h2, l2);
        *(__nv_bfloat162*)(aHi + row * PB + k4 * 4) = h2;
        *(__nv_bfloat162*)(aLo + row * PB + k4 * 4) = l2;
        splitp(t2, t3, h2, l2);
        *(__nv_bfloat162*)(aHi + row * PB + k4 * 4 + 2) = h2;
        *(__nv_bfloat162*)(aLo + row * PB + k4 * 4 + 2) = l2;
    }
}

__global__ void __launch_bounds__(256, 2)
k_node_update(const float* __restrict__ w0, const float* __restrict__ b0,
              const float* __restrict__ w1, const float* __restrict__ b1) {
    extern __shared__ char sm[];
    __nv_bfloat16* aHi = (__nv_bfloat16*)sm;
    __nv_bfloat16* aLo = aHi + 128 * PB;
    __nv_bfloat16* w0H = aLo + 128 * PB;
    __nv_bfloat16* w0L = w0H + 64 * PB;
    __nv_bfloat16* w1H = w0L + 64 * PB;
    __nv_bfloat16* w1L = w1H + 64 * PB;
    float* sB0 = (float*)(w1L + 64 * PB);
    float* sB1 = sB0 + 64;
    stage_w(w0, 64, w0H, w0L); stage_w(w1, 64, w1H, w1L);
    stage_b(b0, sB0); stage_b(b1, sB1);
    int tid = threadIdx.x, lane = tid & 31, wid = tid >> 5, m0 = wid * 16;
    long long base = (long long)blockIdx.x * TILE;
    stage_conv(aHi, aLo, base, N_NODES);
    __syncthreads();
    u32 aHiB = su32(aHi), aLoB = su32(aLo);
    float acc[8][4];
    mma_layer<4>(aHiB, aLoB, su32(w0H), su32(w0L), sB0, acc, lane, m0);
    __syncthreads();
    hidden_store(acc, aHi, aLo, lane, m0);
    __syncthreads();
    mma_layer<4>(aHiB, aLoB, su32(w1H), su32(w1L), sB1, acc, lane, m0);
    int r0 = m0 + (lane >> 2), col0 = (lane & 3) * 2;
    long long row0 = base + r0, row1 = row0 + 8;
    #pragma unroll
    for (int nb = 0; nb < 8; nb++) {
        int c = nb * 8 + col0;
        if (row0 < N_NODES) {
            float2 h0 = *(float2*)(g_h + row0 * 64 + c);
            *(float2*)(g_h + row0 * 64 + c) =
                make_float2(fmaxf(h0.x + acc[nb][0], 0.f), fmaxf(h0.y + acc[nb][1], 0.f));
        }
        if (row1 < N_NODES) {
            float2 h1 = *(float2*)(g_h + row1 * 64 + c);
            *(float2*)(g_h + row1 * 64 + c) =
                make_float2(fmaxf(h1.x + acc[nb][2], 0.f), fmaxf(h1.y + acc[nb][3], 0.f));
        }
    }
}

__global__ void __launch_bounds__(256, 2)
k_node_final(const int* __restrict__ batch,
             const float* __restrict__ w0, const float* __restrict__ b0,
             const float* __restrict__ w1, const float* __restrict__ b1,
             float* __restrict__ out) {
    extern __shared__ char sm[];
    __nv_bfloat16* aHi = (__nv_bfloat16*)sm;
    __nv_bfloat16* aLo = aHi + 128 * PB;
    __nv_bfloat16* w0H = aLo + 128 * PB;
    __nv_bfloat16* w0L = w0H + 64 * PB;
    __nv_bfloat16* w1H = w0L + 64 * PB;
    __nv_bfloat16* w1L = w1H + 64 * PB;
    float* sB0 = (float*)(w1L + 64 * PB);
    float* sB1 = sB0 + 64;
    stage_w(w0, 64, w0H, w0L); stage_w(w1, 64, w1H, w1L);
    stage_b(b0, sB0); stage_b(b1, sB1);
    int tid = threadIdx.x, lane = tid & 31, wid = tid >> 5, m0 = wid * 16;
    long long base = (long long)blockIdx.x * TILE;
    stage_conv(aHi, aLo, base, N_NODES);
    __syncthreads();
    u32 aHiB = su32(aHi), aLoB = su32(aLo);
    float acc[8][4];
    mma_layer<4>(aHiB, aLoB, su32(w0H), su32(w0L), sB0, acc, lane, m0);
    __syncthreads();
    hidden_store(acc, aHi, aLo, lane, m0);
    __syncthreads();
    mma_layer<4>(aHiB, aLoB, su32(w1H), su32(w1L), sB1, acc, lane, m0);
    int r0 = m0 + (lane >> 2), col0 = (lane & 3) * 2;
    long long row0 = base + r0, row1 = row0 + 8;
    int b0g = 0, b1g = 0;
    if (row0 < N_NODES) b0g = __ldg(&batch[row0]);
    if (row1 < N_NODES) b1g = __ldg(&batch[row1]);
    #pragma unroll
    for (int nb = 0; nb < 8; nb++) {
        int c = nb * 8 + col0;
        if (row0 < N_NODES) red2(out + (size_t)b0g * 64 + c, acc[nb][0], acc[nb][1]);
        if (row1 < N_NODES) red2(out + (size_t)b1g * 64 + c, acc[nb][2], acc[nb][3]);
    }
}

__global__ void k_zero_out(float4* out) {
    int i = blockIdx.x * 256 + threadIdx.x;
    out[i] = make_float4(0.f, 0.f, 0.f, 0.f);
}

// Gather (atomic-free, sequential e): 16 lanes per node.
__global__ void __launch_bounds__(256)
k_gather() {
    int gid = blockIdx.x * 256 + threadIdx.x;
    int n = gid >> 4, lane = gid & 15;
    if (n >= N_NODES) return;
    int beg = g_row[n], end = g_row[n + 1];
    float4 acc = make_float4(0.f, 0.f, 0.f, 0.f);
    for (int s = beg; s < end; s++) {
        int src = __ldg(&g_src[s]);
        float4 ev = __ldcs((const float4*)g_e + (size_t)s * 16 + lane);
        float4 hv = __ldg((const float4*)g_h + (size_t)src * 16 + lane);
        acc.x += fmaxf(hv.x + ev.x, 0.f);
        acc.y += fmaxf(hv.y + ev.y, 0.f);
        acc.z += fmaxf(hv.z + ev.z, 0.f);
        acc.w += fmaxf(hv.w + ev.w, 0.f);
    }
    ((float4*)g_agg)[(size_t)n * 16 + lane] = acc;
}

extern "C" void kernel_launch(void* const* d_in, const int* in_sizes, int n_in,
                              void* d_out, int out_size) {
    const float* x   = (const float*)d_in[0];
    const int*   ei  = (const int*)d_in[1];
    const float* ea  = (const float*)d_in[2];
    const int*   bat = (const int*)d_in[3];
    const float* wn0 = (const float*)d_in[4],  *bn0 = (const float*)d_in[5];
    const float* wn1 = (const float*)d_in[6],  *bn1 = (const float*)d_in[7];
    const float* we0 = (const float*)d_in[8],  *be0 = (const float*)d_in[9];
    const float* we1 = (const float*)d_in[10], *be1 = (const float*)d_in[11];
    const float* cw0 = (const float*)d_in[12], *cb0 = (const float*)d_in[13];
    const float* cw1 = (const float*)d_in[14], *cb1 = (const float*)d_in[15];
    const float* lw0 = (const float*)d_in[16], *lb0 = (const float*)d_in[17];
    const float* lw1 = (const float*)d_in[18], *lb1 = (const float*)d_in[19];
    float* out = (float*)d_out;

    const int SM_NODE = (2 * 128 * PB + 2 * 32 * PB + 2 * 64 * PB) * 2 + 2 * 64 * 4;
    const int SM_EDGE = (2 * 128 * PB + 2 * 16 * PB + 2 * 64 * PB) * 2 + 2 * 64 * 4;
    const int SM_CONV = (2 * 128 * PB + 2 * 64 * PB + 2 * 64 * PB) * 2 + 2 * 64 * 4;
    cudaFuncSetAttribute(k_node_init,   cudaFuncAttributeMaxDynamicSharedMemorySize, SM_NODE);
    cudaFuncSetAttribute(k_edge_init,   cudaFuncAttributeMaxDynamicSharedMemorySize, SM_EDGE);
    cudaFuncSetAttribute(k_node_update, cudaFuncAttributeMaxDynamicSharedMemorySize, SM_CONV);
    cudaFuncSetAttribute(k_node_final,  cudaFuncAttributeMaxDynamicSharedMemorySize, SM_CONV);

    const int E256       = (N_EDGES + 255) / 256;
    const int NODE_TILES = (N_NODES + TILE - 1) / TILE;   // 782
    const int EDGE_TILES = (N_EDGES + TILE - 1) / TILE;   // 7813
    const int GATH_BLOCKS = (N_NODES * 16 + 255) / 256;

    // launch index 3 = k_node_init (the slot ncu captures)
    k_zero_row<<<(N_NODES + 1 + 255) / 256, 256>>>();                       // 0
    k_count<<<E256, 256>>>(ei);                                              // 1
    k_scan<<<1, 1024>>>();                                                   // 2
    k_node_init<<<NODE_TILES, 256, SM_NODE>>>(x, wn0, bn0, wn1, bn1);        // 3 <- profiled
    k_fill<<<E256, 256>>>(ei);                                               // 4
    k_edge_init<<<EDGE_TILES, 256, SM_EDGE>>>(ea, we0, be0, we1, be1);       // 5
    k_zero_out<<<(N_GRAPHS * 64 / 4) / 256, 256>>>((float4*)out);            // 6

    for (int l = 0; l < 3; l++) {
        k_gather<<<GATH_BLOCKS, 256>>>();
        k_node_update<<<NODE_TILES, 256, SM_CONV>>>(cw0 + l * 64 * 64, cb0 + l * 64,
                                                    cw1 + l * 64 * 64, cb1 + l * 64);
    }
    k_gather<<<GATH_BLOCKS, 256>>>();
    k_node_final<<<NODE_TILES, 256, SM_CONV>>>(bat, lw0, lb0, lw1, lb1, out);
}

// round 14
// speedup vs baseline: 1.8372x; 1.0595x over previous
#include <cuda_runtime.h>
#include <cuda_bf16.h>

#define N_NODES 100000
#define N_EDGES 1000000
#define N_GRAPHS 512

#define TILE 128           // rows per block
#define PB   72            // bf16 tile pitch (144B rows -> conflict-free LDSM)

typedef unsigned int u32;

// Scratch (device globals — no allocation allowed)
__device__ float g_h[N_NODES * 64];     // node features   (25.6 MB)
__device__ float g_agg[N_NODES * 64];   // gather target   (25.6 MB)
__device__ float g_e[N_EDGES * 64];     // edge embeddings, CSR-permuted (256 MB)
__device__ int   g_row[N_NODES + 1];    // CSR row offsets (by dst)
__device__ int   g_cur[N_NODES];        // fill cursors
__device__ int   g_src[N_EDGES];        // src node per CSR slot
__device__ int   g_pos[N_EDGES];        // edge id -> CSR slot

// ---------------- PTX helpers ----------------
__device__ __forceinline__ u32 su32(const void* p) {
    return (u32)__cvta_generic_to_shared(p);
}
__device__ __forceinline__ void ldsm_x4(u32* r, u32 addr) {
    asm volatile("ldmatrix.sync.aligned.m8n8.x4.shared.b16 {%0,%1,%2,%3}, [%4];"
                 : "=r"(r[0]), "=r"(r[1]), "=r"(r[2]), "=r"(r[3]) : "r"(addr));
}
__device__ __forceinline__ void ldsm_x4t(u32* r, u32 addr) {
    asm volatile("ldmatrix.sync.aligned.m8n8.x4.trans.shared.b16 {%0,%1,%2,%3}, [%4];"
                 : "=r"(r[0]), "=r"(r[1]), "=r"(r[2]), "=r"(r[3]) : "r"(addr));
}
__device__ __forceinline__ void mma_bf16(float* d, const u32* a, const u32* b) {
    asm volatile("mma.sync.aligned.m16n8k16.row.col.f32.bf16.bf16.f32 "
                 "{%0,%1,%2,%3}, {%4,%5,%6,%7}, {%8,%9}, {%0,%1,%2,%3};"
                 : "+f"(d[0]), "+f"(d[1]), "+f"(d[2]), "+f"(d[3])
                 : "r"(a[0]), "r"(a[1]), "r"(a[2]), "r"(a[3]), "r"(b[0]), "r"(b[1]));
}
__device__ __forceinline__ void red2(float* p, float x, float y) {
    asm volatile("red.global.add.v2.f32 [%0], {%1,%2};" :: "l"(p), "f"(x), "f"(y) : "memory");
}

// split a float pair into hi/lo bf16 pairs (error compensation)
__device__ __forceinline__ void splitp(float v0, float v1,
                                       __nv_bfloat162& hi, __nv_bfloat162& lo) {
    __nv_bfloat16 h0 = __float2bfloat16(v0);
    __nv_bfloat16 h1 = __float2bfloat16(v1);
    __nv_bfloat16 l0 = __float2bfloat16(v0 - __bfloat162float(h0));
    __nv_bfloat16 l1 = __float2bfloat16(v1 - __bfloat162float(h1));
    hi = __halves2bfloat162(h0, h1);
    lo = __halves2bfloat162(l0, l1);
}

// ---------------- MMA MLP layer ----------------
// Block = 256 threads = 8 warps; warp w owns rows m0=w*16 .. +16, all 64 cols.
// A tiles (hi/lo) [128][PB] bf16 in smem; W tiles (hi/lo) [K][PB]; bias fp32.
// B fragments loaded two n-blocks at a time via ldmatrix.x4.trans.
template<int KSTEPS>
__device__ __forceinline__ void mma_layer(u32 aHiB, u32 aLoB, u32 wHiB, u32 wLoB,
                                          const float* sB, float acc[8][4],
                                          int lane, int m0) {
    int col0 = (lane & 3) * 2;
    #pragma unroll
    for (int nb = 0; nb < 8; nb++) {
        float b0 = sB[nb * 8 + col0], b1 = sB[nb * 8 + col0 + 1];
        acc[nb][0] = b0; acc[nb][1] = b1; acc[nb][2] = b0; acc[nb][3] = b1;
    }
    int arow = m0 + (lane & 15);
    int acol = (lane >> 4) * 8;
    #pragma unroll
    for (int ks = 0; ks < KSTEPS; ks++) {
        int k0 = ks * 16;
        u32 ah[4], al[4];
        ldsm_x4(ah, aHiB + (u32)((arow * PB + k0 + acol) * 2));
        ldsm_x4(al, aLoB + (u32)((arow * PB + k0 + acol) * 2));
        // B: rows k0+(lane&15), col block (nb2*2 + lane>>4)
        int brow = k0 + (lane & 15);
        int bsel = (lane >> 4);
        #pragma unroll
        for (int nb2 = 0; nb2 < 4; nb2++) {
            u32 bh[4], bl[4];
            u32 boff = (u32)((brow * PB + (nb2 * 2 + bsel) * 8) * 2);
            ldsm_x4t(bh, wHiB + boff);
            ldsm_x4t(bl, wLoB + boff);
            mma_bf16(acc[nb2 * 2],     ah, bh);
            mma_bf16(acc[nb2 * 2],     ah, bl);
            mma_bf16(acc[nb2 * 2],     al, bh);
            mma_bf16(acc[nb2 * 2 + 1], ah, bh + 2);
            mma_bf16(acc[nb2 * 2 + 1], ah, bl + 2);
            mma_bf16(acc[nb2 * 2 + 1], al, bh + 2);
        }
    }
}

// relu + hi/lo split store of acc into A tiles (for layer2 input)
__device__ __forceinline__ void hidden_store(float acc[8][4],
                                             __nv_bfloat16* aHi, __nv_bfloat16* aLo,
                                             int lane, int m0) {
    int r0 = m0 + (lane >> 2), r1 = r0 + 8;
    int col0 = (lane & 3) * 2;
    #pragma unroll
    for (int nb = 0; nb < 8; nb++) {
        int c = nb * 8 + col0;
        float v0 = fmaxf(acc[nb][0], 0.f), v1 = fmaxf(acc[nb][1], 0.f);
        float v2 = fmaxf(acc[nb][2], 0.f), v3 = fmaxf(acc[nb][3], 0.f);
        __nv_bfloat162 h2, l2;
        splitp(v0, v1, h2, l2);
        *(__nv_bfloat162*)(aHi + r0 * PB + c) = h2;
        *(__nv_bfloat162*)(aLo + r0 * PB + c) = l2;
        splitp(v2, v3, h2, l2);
        *(__nv_bfloat162*)(aHi + r1 * PB + c) = h2;
        *(__nv_bfloat162*)(aLo + r1 * PB + c) = l2;
    }
}

// stage fp32 weights [K][64] as hi/lo bf16 tiles
__device__ __forceinline__ void stage_w(const float* __restrict__ w, int K,
                                        __nv_bfloat16* wHi, __nv_bfloat16* wLo) {
    for (int i = threadIdx.x; i < K * 32; i += 256) {
        int k = i >> 5, c2 = (i & 31) * 2;
        __nv_bfloat162 h2, l2;
        splitp(w[k * 64 + c2], w[k * 64 + c2 + 1], h2, l2);
        *(__nv_bfloat162*)(wHi + k * PB + c2) = h2;
        *(__nv_bfloat162*)(wLo + k * PB + c2) = l2;
    }
}
__device__ __forceinline__ void stage_b(const float* __restrict__ b, float* sB) {
    for (int i = threadIdx.x; i < 64; i += 256) sB[i] = b[i];
}

// ---------------- CSR construction ----------------
__global__ void k_zero_row() {
    int i = blockIdx.x * 256 + threadIdx.x;
    if (i <= N_NODES) g_row[i] = 0;
}

__global__ void k_count(const int* __restrict__ ei) {
    int e = blockIdx.x * 256 + threadIdx.x;
    if (e < N_EDGES) atomicAdd(&g_row[ei[N_EDGES + e]], 1);
}

__global__ void __launch_bounds__(1024) k_scan() {
    __shared__ int warp_tot[32];
    __shared__ int carry_s, tot_s;
    int tid = threadIdx.x, lane = tid & 31, wid = tid >> 5;
    if (tid == 0) carry_s = 0;
    __syncthreads();
    for (int base = 0; base < N_NODES; base += 4096) {
        int idx = base + tid * 4;
        int v0 = (idx     < N_NODES) ? g_row[idx]     : 0;
        int v1 = (idx + 1 < N_NODES) ? g_row[idx + 1] : 0;
        int v2 = (idx + 2 < N_NODES) ? g_row[idx + 2] : 0;
        int v3 = (idx + 3 < N_NODES) ? g_row[idx + 3] : 0;
        int s0 = v0, s1 = s0 + v1, s2 = s1 + v2, s3 = s2 + v3;
        int tsum = s3;
        int incl = tsum;
        #pragma unroll
        for (int off = 1; off < 32; off <<= 1) {
            int t = __shfl_up_sync(0xffffffff, incl, off);
            if (lane >= off) incl += t;
        }
        if (lane == 31) warp_tot[wid] = incl;
        __syncthreads();
        if (wid == 0) {
            int w = warp_tot[lane];
            int wi = w;
            #pragma unroll
            for (int off = 1; off < 32; off <<= 1) {
                int t = __shfl_up_sync(0xffffffff, wi, off);
                if (lane >= off) wi += t;
            }
            warp_tot[lane] = wi - w;
            if (lane == 31) tot_s = wi;
        }
        __syncthreads();
        int eb = carry_s + warp_tot[wid] + (incl - tsum);
        if (idx     < N_NODES) { g_row[idx]     = eb;      g_cur[idx]     = eb; }
        if (idx + 1 < N_NODES) { g_row[idx + 1] = eb + s0; g_cur[idx + 1] = eb + s0; }
        if (idx + 2 < N_NODES) { g_row[idx + 2] = eb + s1; g_cur[idx + 2] = eb + s1; }
        if (idx + 3 < N_NODES) { g_row[idx + 3] = eb + s2; g_cur[idx + 3] = eb + s2; }
        __syncthreads();
        if (tid == 0) carry_s += tot_s;
        __syncthreads();
    }
    if (tid == 0) g_row[N_NODES] = N_EDGES;
}

__global__ void k_fill(const int* __restrict__ ei) {
    int e = blockIdx.x * 256 + threadIdx.x;
    if (e >= N_EDGES) return;
    int src = ei[e];
    int dst = ei[N_EDGES + e];
    int p = atomicAdd(&g_cur[dst], 1);
    g_src[p] = src;
    g_pos[e] = p;
}

// ---------------- MLP kernels (tensor-core) ----------------

__global__ void __launch_bounds__(256, 3)
k_node_init(const float* __restrict__ x,
            const float* __restrict__ w0, const float* __restrict__ b0,
            const float* __restrict__ w1, const float* __restrict__ b1) {
    extern __shared__ char sm[];
    __nv_bfloat16* aHi = (__nv_bfloat16*)sm;
    __nv_bfloat16* aLo = aHi + 128 * PB;
    __nv_bfloat16* w0H = aLo + 128 * PB;
    __nv_bfloat16* w0L = w0H + 32 * PB;
    __nv_bfloat16* w1H = w0L + 32 * PB;
    __nv_bfloat16* w1L = w1H + 64 * PB;
    float* sB0 = (float*)(w1L + 64 * PB);
    float* sB1 = sB0 + 64;
    stage_w(w0, 32, w0H, w0L); stage_w(w1, 64, w1H, w1L);
    stage_b(b0, sB0); stage_b(b1, sB1);
    int tid = threadIdx.x, lane = tid & 31, wid = tid >> 5, m0 = wid * 16;
    long long base = (long long)blockIdx.x * TILE;
    for (int i = tid; i < TILE * 8; i += 256) {
        int row = i >> 3, q = i & 7;
        long long gr = base + row; if (gr >= N_NODES) gr = N_NODES - 1;
        float4 v = ((const float4*)(x + gr * 32))[q];
        __nv_bfloat162 h2, l2;
        splitp(v.x, v.y, h2, l2);
        *(__nv_bfloat162*)(aHi + row * PB + q * 4) = h2;
        *(__nv_bfloat162*)(aLo + row * PB + q * 4) = l2;
        splitp(v.z, v.w, h2, l2);
        *(__nv_bfloat162*)(aHi + row * PB + q * 4 + 2) = h2;
        *(__nv_bfloat162*)(aLo + row * PB + q * 4 + 2) = l2;
    }
    __syncthreads();
    u32 aHiB = su32(aHi), aLoB = su32(aLo);
    float acc[8][4];
    mma_layer<2>(aHiB, aLoB, su32(w0H), su32(w0L), sB0, acc, lane, m0);
    __syncthreads();
    hidden_store(acc, aHi, aLo, lane, m0);
    __syncthreads();
    mma_layer<4>(aHiB, aLoB, su32(w1H), su32(w1L), sB1, acc, lane, m0);
    int r0 = m0 + (lane >> 2), col0 = (lane & 3) * 2;
    long long row0 = base + r0, row1 = row0 + 8;
    #pragma unroll
    for (int nb = 0; nb < 8; nb++) {
        int c = nb * 8 + col0;
        if (row0 < N_NODES) *(float2*)(g_h + row0 * 64 + c) = make_float2(acc[nb][0], acc[nb][1]);
        if (row1 < N_NODES) *(float2*)(g_h + row1 * 64 + c) = make_float2(acc[nb][2], acc[nb][3]);
    }
}

__global__ void __launch_bounds__(256, 3)
k_edge_init(const float* __restrict__ ea,
            const float* __restrict__ w0, const float* __restrict__ b0,
            const float* __restrict__ w1, const float* __restrict__ b1) {
    extern __shared__ char sm[];
    __nv_bfloat16* aHi = (__nv_bfloat16*)sm;
    __nv_bfloat16* aLo = aHi + 128 * PB;
    __nv_bfloat16* w0H = aLo + 128 * PB;
    __nv_bfloat16* w0L = w0H + 16 * PB;
    __nv_bfloat16* w1H = w0L + 16 * PB;
    __nv_bfloat16* w1L = w1H + 64 * PB;
    float* sB0 = (float*)(w1L + 64 * PB);
    float* sB1 = sB0 + 64;
    stage_w(w0, 16, w0H, w0L); stage_w(w1, 64, w1H, w1L);
    stage_b(b0, sB0); stage_b(b1, sB1);
    int tid = threadIdx.x, lane = tid & 31, wid = tid >> 5, m0 = wid * 16;
    long long base = (long long)blockIdx.x * TILE;
    for (int i = tid; i < TILE * 4; i += 256) {
        int row = i >> 2, q = i & 3;
        long long gr = base + row; if (gr >= N_EDGES) gr = N_EDGES - 1;
        float4 v = ((const float4*)(ea + gr * 16))[q];
        __nv_bfloat162 h2, l2;
        splitp(v.x, v.y, h2, l2);
        *(__nv_bfloat162*)(aHi + row * PB + q * 4) = h2;
        *(__nv_bfloat162*)(aLo + row * PB + q * 4) = l2;
        splitp(v.z, v.w, h2, l2);
        *(__nv_bfloat162*)(aHi + row * PB + q * 4 + 2) = h2;
        *(__nv_bfloat162*)(aLo + row * PB + q * 4 + 2) = l2;
    }
    __syncthreads();
    u32 aHiB = su32(aHi), aLoB = su32(aLo);
    float acc[8][4];
    mma_layer<1>(aHiB, aLoB, su32(w0H), su32(w0L), sB0, acc, lane, m0);
    __syncthreads();
    hidden_store(acc, aHi, aLo, lane, m0);
    __syncthreads();
    mma_layer<4>(aHiB, aLoB, su32(w1H), su32(w1L), sB1, acc, lane, m0);
    int r0 = m0 + (lane >> 2), col0 = (lane & 3) * 2;
    long long row0 = base + r0, row1 = row0 + 8;
    int p0 = 0, p1 = 0;
    if (row0 < N_EDGES) p0 = __ldg(&g_pos[row0]);
    if (row1 < N_EDGES) p1 = __ldg(&g_pos[row1]);
    #pragma unroll
    for (int nb = 0; nb < 8; nb++) {
        int c = nb * 8 + col0;
        if (row0 < N_EDGES) __stcs((float2*)(g_e + (size_t)p0 * 64 + c), make_float2(acc[nb][0], acc[nb][1]));
        if (row1 < N_EDGES) __stcs((float2*)(g_e + (size_t)p1 * 64 + c), make_float2(acc[nb][2], acc[nb][3]));
    }
}

// conv staging: t = agg + 1.1*h, hi/lo split
__device__ __forceinline__ void stage_conv(__nv_bfloat16* aHi, __nv_bfloat16* aLo,
                                           long long base, long long limit) {
    for (int i = threadIdx.x; i < TILE * 16; i += 256) {
        int row = i >> 4, k4 = i & 15;
        long long gr = base + row; if (gr >= limit) gr = limit - 1;
        float4 a = ((const float4*)(g_agg + gr * 64))[k4];
        float4 h = ((const float4*)(g_h   + gr * 64))[k4];
        float t0 = fmaf(1.1f, h.x, a.x), t1 = fmaf(1.1f, h.y, a.y);
        float t2 = fmaf(1.1f, h.z, a.z), t3 = fmaf(1.1f, h.w, a.w);
        __nv_bfloat162 h2, l2;
        splitp(t0, t1, h2, l2);
        *(__nv_bfloat162*)(aHi + row * PB + k4 * 4) = h2;
        *(__nv_bfloat162*)(aLo + row * PB + k4 * 4) = l2;
        splitp(t2, t3, h2, l2);
        *(__nv_bfloat162*)(aHi + row * PB + k4 * 4 + 2) = h2;
        *(__nv_bfloat162*)(aLo + row * PB + k4 * 4 + 2) = l2;
    }
}

__global__ void __launch_bounds__(256, 3)
k_node_update(const float* __restrict__ w0, const float* __restrict__ b0,
              const float* __restrict__ w1, const float* __restrict__ b1) {
    extern __shared__ char sm[];
    __nv_bfloat16* aHi = (__nv_bfloat16*)sm;
    __nv_bfloat16* aLo = aHi + 128 * PB;
    __nv_bfloat16* w0H = aLo + 128 * PB;
    __nv_bfloat16* w0L = w0H + 64 * PB;
    __nv_bfloat16* w1H = w0L + 64 * PB;
    __nv_bfloat16* w1L = w1H + 64 * PB;
    float* sB0 = (float*)(w1L + 64 * PB);
    float* sB1 = sB0 + 64;
    stage_w(w0, 64, w0H, w0L); stage_w(w1, 64, w1H, w1L);
    stage_b(b0, sB0); stage_b(b1, sB1);
    int tid = threadIdx.x, lane = tid & 31, wid = tid >> 5, m0 = wid * 16;
    long long base = (long long)blockIdx.x * TILE;
    stage_conv(aHi, aLo, base, N_NODES);
    __syncthreads();
    u32 aHiB = su32(aHi), aLoB = su32(aLo);
    float acc[8][4];
    mma_layer<4>(aHiB, aLoB, su32(w0H), su32(w0L), sB0, acc, lane, m0);
    __syncthreads();
    hidden_store(acc, aHi, aLo, lane, m0);
    __syncthreads();
    mma_layer<4>(aHiB, aLoB, su32(w1H), su32(w1L), sB1, acc, lane, m0);
    int r0 = m0 + (lane >> 2), col0 = (lane & 3) * 2;
    long long row0 = base + r0, row1 = row0 + 8;
    #pragma unroll
    for (int nb = 0; nb < 8; nb++) {
        int c = nb * 8 + col0;
        if (row0 < N_NODES) {
            float2 h0 = *(float2*)(g_h + row0 * 64 + c);
            *(float2*)(g_h + row0 * 64 + c) =
                make_float2(fmaxf(h0.x + acc[nb][0], 0.f), fmaxf(h0.y + acc[nb][1], 0.f));
        }
        if (row1 < N_NODES) {
            float2 h1 = *(float2*)(g_h + row1 * 64 + c);
            *(float2*)(g_h + row1 * 64 + c) =
                make_float2(fmaxf(h1.x + acc[nb][2], 0.f), fmaxf(h1.y + acc[nb][3], 0.f));
        }
    }
}

__global__ void __launch_bounds__(256, 3)
k_node_final(const int* __restrict__ batch,
             const float* __restrict__ w0, const float* __restrict__ b0,
             const float* __restrict__ w1, const float* __restrict__ b1,
             float* __restrict__ out) {
    extern __shared__ char sm[];
    __nv_bfloat16* aHi = (__nv_bfloat16*)sm;
    __nv_bfloat16* aLo = aHi + 128 * PB;
    __nv_bfloat16* w0H = aLo + 128 * PB;
    __nv_bfloat16* w0L = w0H + 64 * PB;
    __nv_bfloat16* w1H = w0L + 64 * PB;
    __nv_bfloat16* w1L = w1H + 64 * PB;
    float* sB0 = (float*)(w1L + 64 * PB);
    float* sB1 = sB0 + 64;
    stage_w(w0, 64, w0H, w0L); stage_w(w1, 64, w1H, w1L);
    stage_b(b0, sB0); stage_b(b1, sB1);
    int tid = threadIdx.x, lane = tid & 31, wid = tid >> 5, m0 = wid * 16;
    long long base = (long long)blockIdx.x * TILE;
    stage_conv(aHi, aLo, base, N_NODES);
    __syncthreads();
    u32 aHiB = su32(aHi), aLoB = su32(aLo);
    float acc[8][4];
    mma_layer<4>(aHiB, aLoB, su32(w0H), su32(w0L), sB0, acc, lane, m0);
    __syncthreads();
    hidden_store(acc, aHi, aLo, lane, m0);
    __syncthreads();
    mma_layer<4>(aHiB, aLoB, su32(w1H), su32(w1L), sB1, acc, lane, m0);
    int r0 = m0 + (lane >> 2), col0 = (lane & 3) * 2;
    long long row0 = base + r0, row1 = row0 + 8;
    int b0g = 0, b1g = 0;
    if (row0 < N_NODES) b0g = __ldg(&batch[row0]);
    if (row1 < N_NODES) b1g = __ldg(&batch[row1]);
    #pragma unroll
    for (int nb = 0; nb < 8; nb++) {
        int c = nb * 8 + col0;
        if (row0 < N_NODES) red2(out + (size_t)b0g * 64 + c, acc[nb][0], acc[nb][1]);
        if (row1 < N_NODES) red2(out + (size_t)b1g * 64 + c, acc[nb][2], acc[nb][3]);
    }
}

__global__ void k_zero_out(float4* out) {
    int i = blockIdx.x * 256 + threadIdx.x;
    out[i] = make_float4(0.f, 0.f, 0.f, 0.f);
}

// Gather (atomic-free, sequential e): 16 lanes per node.
__global__ void __launch_bounds__(256)
k_gather() {
    int gid = blockIdx.x * 256 + threadIdx.x;
    int n = gid >> 4, lane = gid & 15;
    if (n >= N_NODES) return;
    int beg = g_row[n], end = g_row[n + 1];
    float4 acc = make_float4(0.f, 0.f, 0.f, 0.f);
    for (int s = beg; s < end; s++) {
        int src = __ldg(&g_src[s]);
        float4 ev = __ldcs((const float4*)g_e + (size_t)s * 16 + lane);
        float4 hv = __ldg((const float4*)g_h + (size_t)src * 16 + lane);
        acc.x += fmaxf(hv.x + ev.x, 0.f);
        acc.y += fmaxf(hv.y + ev.y, 0.f);
        acc.z += fmaxf(hv.z + ev.z, 0.f);
        acc.w += fmaxf(hv.w + ev.w, 0.f);
    }
    ((float4*)g_agg)[(size_t)n * 16 + lane] = acc;
}

extern "C" void kernel_launch(void* const* d_in, const int* in_sizes, int n_in,
                              void* d_out, int out_size) {
    const float* x   = (const float*)d_in[0];
    const int*   ei  = (const int*)d_in[1];
    const float* ea  = (const float*)d_in[2];
    const int*   bat = (const int*)d_in[3];
    const float* wn0 = (const float*)d_in[4],  *bn0 = (const float*)d_in[5];
    const float* wn1 = (const float*)d_in[6],  *bn1 = (const float*)d_in[7];
    const float* we0 = (const float*)d_in[8],  *be0 = (const float*)d_in[9];
    const float* we1 = (const float*)d_in[10], *be1 = (const float*)d_in[11];
    const float* cw0 = (const float*)d_in[12], *cb0 = (const float*)d_in[13];
    const float* cw1 = (const float*)d_in[14], *cb1 = (const float*)d_in[15];
    const float* lw0 = (const float*)d_in[16], *lb0 = (const float*)d_in[17];
    const float* lw1 = (const float*)d_in[18], *lb1 = (const float*)d_in[19];
    float* out = (float*)d_out;

    const int SM_NODE = (2 * 128 * PB + 2 * 32 * PB + 2 * 64 * PB) * 2 + 2 * 64 * 4;
    const int SM_EDGE = (2 * 128 * PB + 2 * 16 * PB + 2 * 64 * PB) * 2 + 2 * 64 * 4;
    const int SM_CONV = (2 * 128 * PB + 2 * 64 * PB + 2 * 64 * PB) * 2 + 2 * 64 * 4;
    cudaFuncSetAttribute(k_node_init,   cudaFuncAttributeMaxDynamicSharedMemorySize, SM_NODE);
    cudaFuncSetAttribute(k_edge_init,   cudaFuncAttributeMaxDynamicSharedMemorySize, SM_EDGE);
    cudaFuncSetAttribute(k_node_update, cudaFuncAttributeMaxDynamicSharedMemorySize, SM_CONV);
    cudaFuncSetAttribute(k_node_final,  cudaFuncAttributeMaxDynamicSharedMemorySize, SM_CONV);

    const int E256       = (N_EDGES + 255) / 256;
    const int NODE_TILES = (N_NODES + TILE - 1) / TILE;   // 782
    const int EDGE_TILES = (N_EDGES + TILE - 1) / TILE;   // 7813
    const int GATH_BLOCKS = (N_NODES * 16 + 255) / 256;

    // launch index 3 = k_node_init (the slot ncu captures)
    k_zero_row<<<(N_NODES + 1 + 255) / 256, 256>>>();                       // 0
    k_count<<<E256, 256>>>(ei);                                              // 1
    k_scan<<<1, 1024>>>();                                                   // 2
    k_node_init<<<NODE_TILES, 256, SM_NODE>>>(x, wn0, bn0, wn1, bn1);        // 3 <- profiled
    k_fill<<<E256, 256>>>(ei);                                               // 4
    k_edge_init<<<EDGE_TILES, 256, SM_EDGE>>>(ea, we0, be0, we1, be1);       // 5
    k_zero_out<<<(N_GRAPHS * 64 / 4) / 256, 256>>>((float4*)out);            // 6

    for (int l = 0; l < 3; l++) {
        k_gather<<<GATH_BLOCKS, 256>>>();
        k_node_update<<<NODE_TILES, 256, SM_CONV>>>(cw0 + l * 64 * 64, cb0 + l * 64,
                                                    cw1 + l * 64 * 64, cb1 + l * 64);
    }
    k_gather<<<GATH_BLOCKS, 256>>>();
    k_node_final<<<NODE_TILES, 256, SM_CONV>>>(bat, lw0, lb0, lw1, lb1, out);
}